// round 14
// baseline (speedup 1.0000x reference)
#include <cuda_runtime.h>
#include <cuda_fp16.h>
#include <math.h>
#include <stdint.h>

#define BB   2
#define TT   2048
#define CC   1024
#define HH   16
#define HD   64
#define MROWS (BB*TT)        // 4096
#define N_QKV (3*CC)         // 3072

// ---------------------------------------------------------------------------
// Scratch (device globals) — fp16
// ---------------------------------------------------------------------------
__device__ __align__(1024) __half g_q[BB*HH*TT*HD];   // [B,H,T,HD], pre-scaled by 0.125*log2e
__device__ __align__(1024) __half g_k[BB*HH*TT*HD];   // [B,H,T,HD]
__device__ __align__(1024) __half g_v[BB*HH*TT*HD];   // [B,H,HD,T]  (TRANSPOSED)
__device__ __align__(1024) __half g_y[MROWS*CC];      // attn out
__device__ __align__(1024) __half g_xp[MROWS*CC];     // x
__device__ __align__(1024) __half g_wtq[N_QKV*CC];    // Wqkv^T
__device__ __align__(1024) __half g_wtp[CC*CC];       // Wproj^T
__device__ int g_fq[32];                              // per-m-block QKV flags
__device__ int g_fy[32];                              // per-m-block attn-out flags

// ---------------------------------------------------------------------------
// Helpers
// ---------------------------------------------------------------------------
__device__ __forceinline__ float ex2(float x) {
    float r;
    asm("ex2.approx.f32 %0, %1;" : "=f"(r) : "f"(x));
    return r;
}

__device__ __forceinline__ uint32_t pack_h2(float lo, float hi) {
    uint32_t r;
    asm("cvt.rn.f16x2.f32 %0, %1, %2;" : "=r"(r) : "f"(hi), "f"(lo));
    return r;
}

__device__ __forceinline__ uint32_t s2u(const void* p) {
    uint32_t a;
    asm("{ .reg .u64 t; cvta.to.shared.u64 t, %1; cvt.u32.u64 %0, t; }"
        : "=r"(a) : "l"(p));
    return a;
}

__device__ __forceinline__ void cp_async16(uint32_t dst, const void* src) {
    asm volatile("cp.async.cg.shared.global [%0], [%1], 16;"
                 :: "r"(dst), "l"(src) : "memory");
}

__device__ __forceinline__ void ldsm4(uint32_t r[4], uint32_t addr) {
    asm volatile("ldmatrix.sync.aligned.m8n8.x4.shared.b16 {%0,%1,%2,%3}, [%4];"
                 : "=r"(r[0]), "=r"(r[1]), "=r"(r[2]), "=r"(r[3]) : "r"(addr));
}

__device__ __forceinline__ void mma_f16(float d[4], uint32_t a0, uint32_t a1,
                                        uint32_t a2, uint32_t a3,
                                        uint32_t b0, uint32_t b1)
{
    asm volatile(
        "mma.sync.aligned.m16n8k16.row.col.f32.f16.f16.f32 "
        "{%0,%1,%2,%3}, {%4,%5,%6,%7}, {%8,%9}, {%0,%1,%2,%3};"
        : "+f"(d[0]), "+f"(d[1]), "+f"(d[2]), "+f"(d[3])
        : "r"(a0), "r"(a1), "r"(a2), "r"(a3), "r"(b0), "r"(b1));
}

__device__ __forceinline__ void spin_flag(int* flags, int idx, int target) {
    while (*((volatile int*)&flags[idx]) < target) __nanosleep(64);
}

// ---------------------------------------------------------------------------
// Combined prep kernel (one launch)
// ---------------------------------------------------------------------------
__global__ void prep_all(const float* __restrict__ x,
                         const float* __restrict__ Wqkv,
                         const float* __restrict__ Wproj,
                         __half* __restrict__ xp,
                         __half* __restrict__ wtq,
                         __half* __restrict__ wtp)
{
    const int bid = blockIdx.x;
    const int tid = threadIdx.x;
    if (bid == 0 && tid < 64) {
        if (tid < 32) g_fq[tid] = 0;
        else          g_fy[tid - 32] = 0;
    }
    if (bid < 4096) {
        int i = bid * 256 + tid;
        float4 v = ((const float4*)x)[i];
        uint2 o;
        o.x = pack_h2(v.x, v.y);
        o.y = pack_h2(v.z, v.w);
        ((uint2*)xp)[i] = o;
        return;
    }
    __shared__ float t[32][33];
    const float* in;
    __half* out;
    int R, C, bx, by;
    if (bid < 4096 + 3072) {
        int tb = bid - 4096;
        in = Wqkv; out = wtq; R = CC; C = N_QKV;
        bx = tb % 96; by = tb / 96;
    } else {
        int tb = bid - 4096 - 3072;
        in = Wproj; out = wtp; R = CC; C = CC;
        bx = tb & 31; by = tb >> 5;
    }
    int xx = tid & 31, yy = tid >> 5;
    int c0 = bx * 32, r0 = by * 32;
#pragma unroll
    for (int i = 0; i < 32; i += 8)
        t[yy + i][xx] = in[(size_t)(r0 + yy + i) * C + c0 + xx];
    __syncthreads();
#pragma unroll
    for (int i = 0; i < 32; i += 8)
        out[(size_t)(c0 + yy + i) * R + r0 + xx] = __float2half_rn(t[xx][yy + i]);
}

// ---------------------------------------------------------------------------
// GEMM tiling: CTA 128x128, K-block 64 (fp16), 3-stage cp.async, 2 CTAs/SM.
// ---------------------------------------------------------------------------
#define GSTAGES 3
#define KB      64
#define HSTR    72
#define TILEH   (128*HSTR)
#define TILE_B  (TILEH*2)
#define GEMM_SMEM (GSTAGES*2*TILE_B)

#define AT_STR  72
#define AT_BUF  (64*AT_STR*2)

__device__ __forceinline__ void g_load_stage(uint32_t sbase, int s,
                                             const __half* Ag, const __half* Bg,
                                             int k0, int tid)
{
    uint32_t base = sbase + (uint32_t)s * 2 * TILE_B;
#pragma unroll
    for (int i = 0; i < 8; i++) {
        int f = tid + i * 128;
        int row = f >> 3, c = f & 7;
        cp_async16(base + row * (HSTR * 2) + c * 16,
                   Ag + (size_t)row * CC + k0 + c * 8);
        cp_async16(base + TILE_B + row * (HSTR * 2) + c * 16,
                   Bg + (size_t)row * CC + k0 + c * 8);
    }
    asm volatile("cp.async.commit_group;" ::: "memory");
}

// Fragment loaders for the GEMM warp geometry
__device__ __forceinline__ void ld_chunk_ab(uint32_t au[4][4], uint32_t bu[4][4],
                                            uint32_t Aab, uint32_t Bab,
                                            int aRow, int aCol, int bRow,
                                            int bCol, int h)
{
#pragma unroll
    for (int mt = 0; mt < 4; mt++)
        ldsm4(au[mt], Aab + (uint32_t)(((aRow + mt * 16) * HSTR
                                        + h * 16 + aCol) * 2));
#pragma unroll
    for (int p = 0; p < 4; p++)
        ldsm4(bu[p], Bab + (uint32_t)(((bRow + p * 16) * HSTR
                                       + h * 16 + bCol) * 2));
}

// Shared fp16 GEMM mainloop with fragment ping-pong (LDSM hidden behind MMA)
__device__ __forceinline__ void gemm_mainloop(uint32_t sbase,
                                              const __half* Ag, const __half* Bg,
                                              int tid, int wm, int wn, int lane,
                                              float acc[4][8][4])
{
    const int aRow = wm * 64 + (lane & 15);
    const int aCol = ((lane >> 4) & 1) * 8;
    const int bRow = wn * 64 + ((lane >> 4) << 3) + (lane & 7);
    const int bCol = ((lane >> 3) & 1) * 8;

    const int NIT = CC / KB;   // 16
#pragma unroll
    for (int s = 0; s < GSTAGES - 1; s++)
        g_load_stage(sbase, s, Ag, Bg, s * KB, tid);

    for (int it = 0; it < NIT; it++) {
        if (it < NIT - 1)
            asm volatile("cp.async.wait_group %0;" :: "n"(GSTAGES - 2) : "memory");
        else
            asm volatile("cp.async.wait_group 0;" ::: "memory");
        __syncthreads();

        if (it + GSTAGES - 1 < NIT)
            g_load_stage(sbase, (it + GSTAGES - 1) % GSTAGES, Ag, Bg,
                         (it + GSTAGES - 1) * KB, tid);

        const uint32_t Aab = sbase + (uint32_t)(it % GSTAGES) * 2 * TILE_B;
        const uint32_t Bab = Aab + TILE_B;

        uint32_t au[2][4][4], bu[2][4][4];
        ld_chunk_ab(au[0], bu[0], Aab, Bab, aRow, aCol, bRow, bCol, 0);
#pragma unroll
        for (int h = 0; h < 4; h++) {
            const int cur = h & 1;
            if (h < 3)
                ld_chunk_ab(au[cur ^ 1], bu[cur ^ 1], Aab, Bab,
                            aRow, aCol, bRow, bCol, h + 1);
#pragma unroll
            for (int mt = 0; mt < 4; mt++)
#pragma unroll
                for (int nt = 0; nt < 8; nt++)
                    mma_f16(acc[mt][nt], au[cur][mt][0], au[cur][mt][1],
                            au[cur][mt][2], au[cur][mt][3],
                            bu[cur][nt >> 1][(nt & 1) * 2],
                            bu[cur][nt >> 1][(nt & 1) * 2 + 1]);
        }
    }
}

// ---------------------------------------------------------------------------
// Mega-kernel:
//   bids    0.. 767 : QKV GEMM, DESCENDING-t m-blocks (release g_fq)
//   bids  768..1791 : flash attention, DESCENDING k-tiles (g_fq -> g_fy)
//   bids 1792..2047 : proj GEMM heavy-first (consume g_fy)
// ---------------------------------------------------------------------------
__global__ __launch_bounds__(128, 2)
void mega_kernel(const __half* __restrict__ A, const __half* __restrict__ Bt,
                 const float* __restrict__ bias, __half* __restrict__ Yg,
                 const __half* __restrict__ Wp, const float* __restrict__ bp,
                 float* __restrict__ Out)
{
    extern __shared__ __align__(16) __half smh[];
    const uint32_t sbase = s2u(smh);
    const int tid = threadIdx.x;
    const int bid = blockIdx.x;
    const int lane = tid & 31;
    const int r    = lane >> 2;
    const int l4   = lane & 3;

    if (bid < 768) {
        // ================= QKV GEMM (descending-t production) ==============
        const int wid = tid >> 5;
        const int wm  = wid & 1;
        const int wn  = wid >> 1;
        const int rank = bid / 24, nblk = bid % 24;
        const int mblock = ((rank & 1) << 4) | (15 - (rank >> 1));
        const int m0 = mblock << 7, n0 = nblk << 7;

        float acc[4][8][4];
#pragma unroll
        for (int mt = 0; mt < 4; mt++)
#pragma unroll
            for (int nt = 0; nt < 8; nt++)
#pragma unroll
                for (int j = 0; j < 4; j++) acc[mt][nt][j] = 0.0f;

        gemm_mainloop(sbase, A + (size_t)m0 * CC, Bt + (size_t)n0 * CC,
                      tid, wm, wn, lane, acc);

        const float QS = 0.125f * 1.44269504089f;
#pragma unroll
        for (int mt = 0; mt < 4; mt++) {
#pragma unroll
            for (int nt = 0; nt < 8; nt++) {
                const int row = m0 + wm * 64 + mt * 16 + r;
                const int c   = n0 + wn * 64 + nt * 8 + 2 * l4;
                const float b0v = __ldg(bias + c);
                const float b1v = __ldg(bias + c + 1);
                float v00 = acc[mt][nt][0] + b0v, v01 = acc[mt][nt][1] + b1v;
                float v10 = acc[mt][nt][2] + b0v, v11 = acc[mt][nt][3] + b1v;
                const int sec = c >> 10;
                const int cs = c & 1023, h = cs >> 6, d0 = cs & 63;
                const int b  = row >> 11;
                const int t0 = row & 2047;
                const int t1 = (row + 8) & 2047;
                if (sec == 2) {
                    __half* vb = g_v + ((size_t)(b * HH + h) * HD) * TT;
                    vb[(size_t)d0 * TT + t0]       = __float2half_rn(v00);
                    vb[(size_t)(d0 + 1) * TT + t0] = __float2half_rn(v01);
                    vb[(size_t)d0 * TT + t1]       = __float2half_rn(v10);
                    vb[(size_t)(d0 + 1) * TT + t1] = __float2half_rn(v11);
                } else {
                    if (sec == 0) { v00 *= QS; v01 *= QS; v10 *= QS; v11 *= QS; }
                    __half* basep = (sec == 0) ? g_q : g_k;
                    __half* p0 = basep + (((size_t)(b * HH + h) * TT + t0) * HD + d0);
                    __half* p1 = basep + (((size_t)(b * HH + h) * TT + t1) * HD + d0);
                    *(uint32_t*)p0 = pack_h2(v00, v01);
                    *(uint32_t*)p1 = pack_h2(v10, v11);
                }
            }
        }
        __syncthreads();
        __threadfence();
        if (tid == 0) atomicAdd(&g_fq[mblock], 1);
        return;
    }

    if (bid >= 1792) {
        // ================= Proj GEMM (consumes g_fy, heavy-first) ===========
        const int pbid = bid - 1792;
        const int wid = tid >> 5;
        const int wm  = wid & 1;
        const int wn  = wid >> 1;
        const int rank = pbid >> 3, nblk = pbid & 7;
        const int mb_w = 15 - (rank >> 1);
        const int b    = rank & 1;
        const int mblock = b * 16 + mb_w;
        const int m0 = mblock << 7, n0 = nblk << 7;

        if (tid == 0) {
            spin_flag(g_fy, mblock, 32);
            __threadfence();
        }
        __syncthreads();

        float acc[4][8][4];
#pragma unroll
        for (int mt = 0; mt < 4; mt++)
#pragma unroll
            for (int nt = 0; nt < 8; nt++)
#pragma unroll
                for (int j = 0; j < 4; j++) acc[mt][nt][j] = 0.0f;

        gemm_mainloop(sbase, Yg + (size_t)m0 * CC, Wp + (size_t)n0 * CC,
                      tid, wm, wn, lane, acc);

#pragma unroll
        for (int mt = 0; mt < 4; mt++) {
#pragma unroll
            for (int nt = 0; nt < 8; nt++) {
                const int row = m0 + wm * 64 + mt * 16 + r;
                const int c   = n0 + wn * 64 + nt * 8 + 2 * l4;
                const float b0v = __ldg(bp + c);
                const float b1v = __ldg(bp + c + 1);
                *(float2*)(Out + (size_t)row * CC + c)
                    = make_float2(acc[mt][nt][0] + b0v, acc[mt][nt][1] + b1v);
                *(float2*)(Out + (size_t)(row + 8) * CC + c)
                    = make_float2(acc[mt][nt][2] + b0v, acc[mt][nt][3] + b1v);
            }
        }
        return;
    }

    // ======= Flash attention (q-tile 64, 4 warps, DESCENDING k-tiles) ======
    {
        const int abid = bid - 768;
        const int qb   = 31 - (abid >> 5);          // heavy-first
        const int bh   = abid & 31;
        const int b    = bh >> 4, h = bh & 15;
        const int qbase = qb * 64;
        const int bqoff  = b * 16;
        const int w = tid >> 5;

        const uint32_t koff = (uint32_t)AT_BUF;
        const uint32_t PS_B = (uint32_t)(4 * 64 * AT_STR * 2);

        const __half* Qp  = g_q + (size_t)bh * TT * HD;
        const __half* Kp  = g_k + (size_t)bh * TT * HD;
        const __half* Vtp = g_v + (size_t)bh * HD * TT;

        if (tid == 0) {
            spin_flag(g_fq, bqoff + (qb >> 1), 24);
            if (qb >= 1) spin_flag(g_fq, bqoff + ((qb - 1) >> 1), 24);
            __threadfence();
        }
        __syncthreads();

        // Q (64x64) into Ps; K/V tile kt0=qb into buffer (qb & 1)
        {
            const int kb0 = qbase;
            const uint32_t buf0 = (uint32_t)(qb & 1);
#pragma unroll
            for (int i = 0; i < 4; i++) {
                int f = tid + i * 128;
                int row = f >> 3, c = f & 7;
                cp_async16(sbase + PS_B + (uint32_t)(row * AT_STR) * 2 + c * 16,
                           Qp + (size_t)(qbase + row) * HD + c * 8);
                cp_async16(sbase + buf0 * koff + (uint32_t)(row * AT_STR) * 2 + c * 16,
                           Kp + (size_t)(kb0 + row) * HD + c * 8);
                cp_async16(sbase + 2 * koff + buf0 * koff
                           + (uint32_t)(row * AT_STR) * 2 + c * 16,
                           Vtp + (size_t)row * TT + kb0 + c * 8);
            }
        }
        asm volatile("cp.async.commit_group;" ::: "memory");
        asm volatile("cp.async.wait_group 0;" ::: "memory");
        __syncthreads();

        const int aRowL = lane & 15;
        const int aColL = ((lane >> 4) & 1) * 8;
        const int bRowL = ((lane >> 4) << 3) + (lane & 7);
        const int bColL = ((lane >> 3) & 1) * 8;

        uint32_t aq[4][4];
#pragma unroll
        for (int hc = 0; hc < 4; hc++)
            ldsm4(aq[hc], sbase + PS_B +
                  (uint32_t)(((w * 16 + aRowL) * AT_STR + hc * 16 + aColL) * 2));
        __syncthreads();   // Ps now free for P

        float O[8][4];
#pragma unroll
        for (int nt = 0; nt < 8; nt++)
#pragma unroll
            for (int j = 0; j < 4; j++) O[nt][j] = 0.0f;
        float m0v = -1e30f, m1v = -1e30f, l0v = 0.0f, l1v = 0.0f;

        const int tq0 = qbase + w * 16 + r;
        const int tq1 = tq0 + 8;
        __half* pw = smh + 4 * 64 * AT_STR + (w * 16) * AT_STR;
        const uint32_t pwAddr = sbase + PS_B + (uint32_t)(w * 16 * AT_STR * 2);

        for (int kt = qb; kt >= 0; kt--) {
            const int kbase = kt * 64;
            const int buf = kt & 1;
            const uint32_t kAddr = sbase + (uint32_t)buf * koff;
            const uint32_t vAddr = sbase + 2 * koff + (uint32_t)buf * koff;
            const bool more = (kt > 0);

            if (more) {
                const int nb = kbase - 64;
                uint32_t kd = sbase + (uint32_t)(buf ^ 1) * koff;
                uint32_t vd = sbase + 2 * koff + (uint32_t)(buf ^ 1) * koff;
#pragma unroll
                for (int i = 0; i < 4; i++) {
                    int f = tid + i * 128;
                    int row = f >> 3, c = f & 7;
                    cp_async16(kd + (uint32_t)(row * AT_STR) * 2 + c * 16,
                               Kp + (size_t)(nb + row) * HD + c * 8);
                    cp_async16(vd + (uint32_t)(row * AT_STR) * 2 + c * 16,
                               Vtp + (size_t)row * TT + nb + c * 8);
                }
                asm volatile("cp.async.commit_group;" ::: "memory");
            }

            // S = Q K^T — K fragments ping-ponged
            float s[8][4];
#pragma unroll
            for (int nt = 0; nt < 8; nt++)
#pragma unroll
                for (int j = 0; j < 4; j++) s[nt][j] = 0.0f;
            {
                uint32_t ku[2][4][4];
#pragma unroll
                for (int p = 0; p < 4; p++)
                    ldsm4(ku[0][p], kAddr + (uint32_t)(((p * 16 + bRowL) * AT_STR
                                                       + bColL) * 2));
#pragma unroll
                for (int hc = 0; hc < 4; hc++) {
                    const int cur = hc & 1;
                    if (hc < 3) {
#pragma unroll
                        for (int p = 0; p < 4; p++)
                            ldsm4(ku[cur ^ 1][p],
                                  kAddr + (uint32_t)(((p * 16 + bRowL) * AT_STR
                                                     + (hc + 1) * 16 + bColL) * 2));
                    }
#pragma unroll
                    for (int nt = 0; nt < 8; nt++)
                        mma_f16(s[nt], aq[hc][0], aq[hc][1], aq[hc][2], aq[hc][3],
                                ku[cur][nt >> 1][(nt & 1) * 2],
                                ku[cur][nt >> 1][(nt & 1) * 2 + 1]);
                }
            }

            // causal mask (diagonal tile only; processed FIRST now)
            if (kbase + 63 > qbase + w * 16) {
#pragma unroll
                for (int nt = 0; nt < 8; nt++) {
                    int tk = kbase + nt * 8 + 2 * l4;
                    if (tk     > tq0) s[nt][0] = -1e30f;
                    if (tk + 1 > tq0) s[nt][1] = -1e30f;
                    if (tk     > tq1) s[nt][2] = -1e30f;
                    if (tk + 1 > tq1) s[nt][3] = -1e30f;
                }
            }

            // online softmax (log2 domain)
            float ml0 = -1e30f, ml1 = -1e30f;
#pragma unroll
            for (int nt = 0; nt < 8; nt++) {
                ml0 = fmaxf(ml0, fmaxf(s[nt][0], s[nt][1]));
                ml1 = fmaxf(ml1, fmaxf(s[nt][2], s[nt][3]));
            }
            ml0 = fmaxf(ml0, __shfl_xor_sync(0xffffffffu, ml0, 1));
            ml0 = fmaxf(ml0, __shfl_xor_sync(0xffffffffu, ml0, 2));
            ml1 = fmaxf(ml1, __shfl_xor_sync(0xffffffffu, ml1, 1));
            ml1 = fmaxf(ml1, __shfl_xor_sync(0xffffffffu, ml1, 2));
            float mn0 = fmaxf(m0v, ml0), mn1 = fmaxf(m1v, ml1);
            float c0 = ex2(m0v - mn0), c1 = ex2(m1v - mn1);
            float ps0 = 0.0f, ps1 = 0.0f;
#pragma unroll
            for (int nt = 0; nt < 8; nt++) {
                s[nt][0] = ex2(s[nt][0] - mn0); ps0 += s[nt][0];
                s[nt][1] = ex2(s[nt][1] - mn0); ps0 += s[nt][1];
                s[nt][2] = ex2(s[nt][2] - mn1); ps1 += s[nt][2];
                s[nt][3] = ex2(s[nt][3] - mn1); ps1 += s[nt][3];
            }
            ps0 += __shfl_xor_sync(0xffffffffu, ps0, 1);
            ps0 += __shfl_xor_sync(0xffffffffu, ps0, 2);
            ps1 += __shfl_xor_sync(0xffffffffu, ps1, 1);
            ps1 += __shfl_xor_sync(0xffffffffu, ps1, 2);
            l0v = l0v * c0 + ps0; m0v = mn0;
            l1v = l1v * c1 + ps1; m1v = mn1;
#pragma unroll
            for (int nt = 0; nt < 8; nt++) {
                O[nt][0] *= c0; O[nt][1] *= c0;
                O[nt][2] *= c1; O[nt][3] *= c1;
            }

            // P -> per-warp smem as half2
#pragma unroll
            for (int nt = 0; nt < 8; nt++) {
                *(uint32_t*)(pw + r * AT_STR + nt * 8 + 2 * l4)
                    = pack_h2(s[nt][0], s[nt][1]);
                *(uint32_t*)(pw + (r + 8) * AT_STR + nt * 8 + 2 * l4)
                    = pack_h2(s[nt][2], s[nt][3]);
            }
            __syncwarp();

            // O += P V — P and V fragments ping-ponged
            {
                uint32_t pa[2][4], vu[2][4][4];
                ldsm4(pa[0], pwAddr + (uint32_t)((aRowL * AT_STR + aColL) * 2));
#pragma unroll
                for (int p = 0; p < 4; p++)
                    ldsm4(vu[0][p], vAddr + (uint32_t)(((p * 16 + bRowL) * AT_STR
                                                       + bColL) * 2));
#pragma unroll
                for (int hc = 0; hc < 4; hc++) {
                    const int cur = hc & 1;
                    if (hc < 3) {
                        ldsm4(pa[cur ^ 1],
                              pwAddr + (uint32_t)((aRowL * AT_STR
                                                   + (hc + 1) * 16 + aColL) * 2));
#pragma unroll
                        for (int p = 0; p < 4; p++)
                            ldsm4(vu[cur ^ 1][p],
                                  vAddr + (uint32_t)(((p * 16 + bRowL) * AT_STR
                                                     + (hc + 1) * 16 + bColL) * 2));
                    }
#pragma unroll
                    for (int nt = 0; nt < 8; nt++)
                        mma_f16(O[nt], pa[cur][0], pa[cur][1], pa[cur][2],
                                pa[cur][3], vu[cur][nt >> 1][(nt & 1) * 2],
                                vu[cur][nt >> 1][(nt & 1) * 2 + 1]);
                }
            }

            if (more) {
                asm volatile("cp.async.wait_group 0;" ::: "memory");
                if (tid == 0) {
                    if (kt - 2 >= 0) spin_flag(g_fq, bqoff + ((kt - 2) >> 1), 24);
                    __threadfence();
                }
                __syncthreads();
            }
        }

        // Epilogue: normalize, half y, release g_fy
        const int hb = h * 64;
        const float inv0 = 1.0f / l0v, inv1 = 1.0f / l1v;
        __half* y0 = Yg + (size_t)(b * TT + tq0) * CC;
        __half* y1 = Yg + (size_t)(b * TT + tq1) * CC;
#pragma unroll
        for (int nt = 0; nt < 8; nt++) {
            int c = hb + nt * 8 + 2 * l4;
            *(uint32_t*)(y0 + c) = pack_h2(O[nt][0] * inv0, O[nt][1] * inv0);
            *(uint32_t*)(y1 + c) = pack_h2(O[nt][2] * inv1, O[nt][3] * inv1);
        }
        __syncthreads();
        __threadfence();
        if (tid == 0) atomicAdd(&g_fy[b * 16 + (qb >> 1)], 1);
    }
}

// ---------------------------------------------------------------------------
// Launch
// ---------------------------------------------------------------------------
extern "C" void kernel_launch(void* const* d_in, const int* in_sizes, int n_in,
                              void* d_out, int out_size)
{
    const float* x     = (const float*)d_in[0];
    const float* Wqkv  = (const float*)d_in[1];
    const float* bqkv  = (const float*)d_in[2];
    const float* Wproj = (const float*)d_in[3];
    const float* bproj = (const float*)d_in[4];
    float* out = (float*)d_out;
    (void)in_sizes; (void)n_in; (void)out_size;

    __half *yp, *xp, *wtq, *wtp;
    cudaGetSymbolAddress((void**)&yp,  g_y);
    cudaGetSymbolAddress((void**)&xp,  g_xp);
    cudaGetSymbolAddress((void**)&wtq, g_wtq);
    cudaGetSymbolAddress((void**)&wtp, g_wtp);

    cudaFuncSetAttribute(mega_kernel, cudaFuncAttributeMaxDynamicSharedMemorySize, GEMM_SMEM);

    prep_all<<<4096 + 3072 + 1024, 256>>>(x, Wqkv, Wproj, xp, wtq, wtp);

    mega_kernel<<<768 + 1024 + 256, 128, GEMM_SMEM>>>(xp, wtq, bqkv, yp,
                                                      wtp, bproj, out);
}

// round 15
// speedup vs baseline: 1.1212x; 1.1212x over previous
#include <cuda_runtime.h>
#include <cuda_fp16.h>
#include <math.h>
#include <stdint.h>

#define BB   2
#define TT   2048
#define CC   1024
#define HH   16
#define HD   64
#define MROWS (BB*TT)        // 4096
#define N_QKV (3*CC)         // 3072

// ---------------------------------------------------------------------------
// Scratch (device globals) — fp16
// ---------------------------------------------------------------------------
__device__ __align__(1024) __half g_q[BB*HH*TT*HD];   // [B,H,T,HD], pre-scaled by 0.125*log2e
__device__ __align__(1024) __half g_k[BB*HH*TT*HD];   // [B,H,T,HD]
__device__ __align__(1024) __half g_v[BB*HH*TT*HD];   // [B,H,HD,T]  (TRANSPOSED)
__device__ __align__(1024) __half g_y[MROWS*CC];      // attn out
__device__ __align__(1024) __half g_xp[MROWS*CC];     // x
__device__ __align__(1024) __half g_wtq[N_QKV*CC];    // Wqkv^T
__device__ __align__(1024) __half g_wtp[CC*CC];       // Wproj^T
__device__ int g_fq[32];                              // per-m-block QKV flags
__device__ int g_fy[32];                              // per-m-block attn-out flags

// ---------------------------------------------------------------------------
// Helpers
// ---------------------------------------------------------------------------
__device__ __forceinline__ float ex2(float x) {
    float r;
    asm("ex2.approx.f32 %0, %1;" : "=f"(r) : "f"(x));
    return r;
}

__device__ __forceinline__ uint32_t pack_h2(float lo, float hi) {
    uint32_t r;
    asm("cvt.rn.f16x2.f32 %0, %1, %2;" : "=r"(r) : "f"(hi), "f"(lo));
    return r;
}

__device__ __forceinline__ uint32_t s2u(const void* p) {
    uint32_t a;
    asm("{ .reg .u64 t; cvta.to.shared.u64 t, %1; cvt.u32.u64 %0, t; }"
        : "=r"(a) : "l"(p));
    return a;
}

__device__ __forceinline__ void cp_async16(uint32_t dst, const void* src) {
    asm volatile("cp.async.cg.shared.global [%0], [%1], 16;"
                 :: "r"(dst), "l"(src) : "memory");
}

__device__ __forceinline__ void ldsm4(uint32_t r[4], uint32_t addr) {
    asm volatile("ldmatrix.sync.aligned.m8n8.x4.shared.b16 {%0,%1,%2,%3}, [%4];"
                 : "=r"(r[0]), "=r"(r[1]), "=r"(r[2]), "=r"(r[3]) : "r"(addr));
}

__device__ __forceinline__ void mma_f16(float d[4], uint32_t a0, uint32_t a1,
                                        uint32_t a2, uint32_t a3,
                                        uint32_t b0, uint32_t b1)
{
    asm volatile(
        "mma.sync.aligned.m16n8k16.row.col.f32.f16.f16.f32 "
        "{%0,%1,%2,%3}, {%4,%5,%6,%7}, {%8,%9}, {%0,%1,%2,%3};"
        : "+f"(d[0]), "+f"(d[1]), "+f"(d[2]), "+f"(d[3])
        : "r"(a0), "r"(a1), "r"(a2), "r"(a3), "r"(b0), "r"(b1));
}

__device__ __forceinline__ void spin_flag(int* flags, int idx, int target) {
    while (*((volatile int*)&flags[idx]) < target) __nanosleep(64);
}

// ---------------------------------------------------------------------------
// Combined prep kernel (one launch)
// ---------------------------------------------------------------------------
__global__ void prep_all(const float* __restrict__ x,
                         const float* __restrict__ Wqkv,
                         const float* __restrict__ Wproj,
                         __half* __restrict__ xp,
                         __half* __restrict__ wtq,
                         __half* __restrict__ wtp)
{
    const int bid = blockIdx.x;
    const int tid = threadIdx.x;
    if (bid == 0 && tid < 64) {
        if (tid < 32) g_fq[tid] = 0;
        else          g_fy[tid - 32] = 0;
    }
    if (bid < 4096) {
        int i = bid * 256 + tid;
        float4 v = ((const float4*)x)[i];
        uint2 o;
        o.x = pack_h2(v.x, v.y);
        o.y = pack_h2(v.z, v.w);
        ((uint2*)xp)[i] = o;
        return;
    }
    __shared__ float t[32][33];
    const float* in;
    __half* out;
    int R, C, bx, by;
    if (bid < 4096 + 3072) {
        int tb = bid - 4096;
        in = Wqkv; out = wtq; R = CC; C = N_QKV;
        bx = tb % 96; by = tb / 96;
    } else {
        int tb = bid - 4096 - 3072;
        in = Wproj; out = wtp; R = CC; C = CC;
        bx = tb & 31; by = tb >> 5;
    }
    int xx = tid & 31, yy = tid >> 5;
    int c0 = bx * 32, r0 = by * 32;
#pragma unroll
    for (int i = 0; i < 32; i += 8)
        t[yy + i][xx] = in[(size_t)(r0 + yy + i) * C + c0 + xx];
    __syncthreads();
#pragma unroll
    for (int i = 0; i < 32; i += 8)
        out[(size_t)(c0 + yy + i) * R + r0 + xx] = __float2half_rn(t[xx][yy + i]);
}

// ---------------------------------------------------------------------------
// GEMM tiling: CTA 128x128, K-block 64 (fp16), 3-stage cp.async, 2 CTAs/SM.
// ---------------------------------------------------------------------------
#define GSTAGES 3
#define KB      64
#define HSTR    72
#define TILEH   (128*HSTR)
#define TILE_B  (TILEH*2)
#define GEMM_SMEM (GSTAGES*2*TILE_B)

#define AT_STR  72
#define AT_BUF  (64*AT_STR*2)

__device__ __forceinline__ void g_load_stage(uint32_t sbase, int s,
                                             const __half* Ag, const __half* Bg,
                                             int k0, int tid)
{
    uint32_t base = sbase + (uint32_t)s * 2 * TILE_B;
#pragma unroll
    for (int i = 0; i < 8; i++) {
        int f = tid + i * 128;
        int row = f >> 3, c = f & 7;
        cp_async16(base + row * (HSTR * 2) + c * 16,
                   Ag + (size_t)row * CC + k0 + c * 8);
        cp_async16(base + TILE_B + row * (HSTR * 2) + c * 16,
                   Bg + (size_t)row * CC + k0 + c * 8);
    }
    asm volatile("cp.async.commit_group;" ::: "memory");
}

// Shared fp16 GEMM mainloop (R13 version — no ping-pong)
__device__ __forceinline__ void gemm_mainloop(uint32_t sbase,
                                              const __half* Ag, const __half* Bg,
                                              int tid, int wm, int wn, int lane,
                                              float acc[4][8][4])
{
    const int aRow = wm * 64 + (lane & 15);
    const int aCol = ((lane >> 4) & 1) * 8;
    const int bRow = wn * 64 + ((lane >> 4) << 3) + (lane & 7);
    const int bCol = ((lane >> 3) & 1) * 8;

    const int NIT = CC / KB;   // 16
#pragma unroll
    for (int s = 0; s < GSTAGES - 1; s++)
        g_load_stage(sbase, s, Ag, Bg, s * KB, tid);

    for (int it = 0; it < NIT; it++) {
        if (it < NIT - 1)
            asm volatile("cp.async.wait_group %0;" :: "n"(GSTAGES - 2) : "memory");
        else
            asm volatile("cp.async.wait_group 0;" ::: "memory");
        __syncthreads();

        if (it + GSTAGES - 1 < NIT)
            g_load_stage(sbase, (it + GSTAGES - 1) % GSTAGES, Ag, Bg,
                         (it + GSTAGES - 1) * KB, tid);

        const uint32_t Aab = sbase + (uint32_t)(it % GSTAGES) * 2 * TILE_B;
        const uint32_t Bab = Aab + TILE_B;

#pragma unroll
        for (int h = 0; h < 4; h++) {
            uint32_t au[4][4];
#pragma unroll
            for (int mt = 0; mt < 4; mt++)
                ldsm4(au[mt], Aab + (uint32_t)(((aRow + mt * 16) * HSTR
                                                + h * 16 + aCol) * 2));
            uint32_t bu[4][4];
#pragma unroll
            for (int p = 0; p < 4; p++)
                ldsm4(bu[p], Bab + (uint32_t)(((bRow + p * 16) * HSTR
                                               + h * 16 + bCol) * 2));
#pragma unroll
            for (int mt = 0; mt < 4; mt++)
#pragma unroll
                for (int nt = 0; nt < 8; nt++)
                    mma_f16(acc[mt][nt], au[mt][0], au[mt][1], au[mt][2],
                            au[mt][3], bu[nt >> 1][(nt & 1) * 2],
                            bu[nt >> 1][(nt & 1) * 2 + 1]);
        }
    }
}

// ---------------------------------------------------------------------------
// Mega-kernel:
//   bids    0.. 767 : QKV GEMM, DESCENDING-t m-blocks (release g_fq)
//   bids  768..1279 : flash attention, q-tile 128, DESCENDING k-tiles
//   bids 1280..1535 : proj GEMM heavy-first (consume g_fy, target 16)
// ---------------------------------------------------------------------------
__global__ __launch_bounds__(128, 2)
void mega_kernel(const __half* __restrict__ A, const __half* __restrict__ Bt,
                 const float* __restrict__ bias, __half* __restrict__ Yg,
                 const __half* __restrict__ Wp, const float* __restrict__ bp,
                 float* __restrict__ Out)
{
    extern __shared__ __align__(16) __half smh[];
    const uint32_t sbase = s2u(smh);
    const int tid = threadIdx.x;
    const int bid = blockIdx.x;
    const int lane = tid & 31;
    const int r    = lane >> 2;
    const int l4   = lane & 3;

    if (bid < 768) {
        // ================= QKV GEMM (descending-t production) ==============
        const int wid = tid >> 5;
        const int wm  = wid & 1;
        const int wn  = wid >> 1;
        const int rank = bid / 24, nblk = bid % 24;
        const int mblock = ((rank & 1) << 4) | (15 - (rank >> 1));
        const int m0 = mblock << 7, n0 = nblk << 7;

        float acc[4][8][4];
#pragma unroll
        for (int mt = 0; mt < 4; mt++)
#pragma unroll
            for (int nt = 0; nt < 8; nt++)
#pragma unroll
                for (int j = 0; j < 4; j++) acc[mt][nt][j] = 0.0f;

        gemm_mainloop(sbase, A + (size_t)m0 * CC, Bt + (size_t)n0 * CC,
                      tid, wm, wn, lane, acc);

        const float QS = 0.125f * 1.44269504089f;
#pragma unroll
        for (int mt = 0; mt < 4; mt++) {
#pragma unroll
            for (int nt = 0; nt < 8; nt++) {
                const int row = m0 + wm * 64 + mt * 16 + r;
                const int c   = n0 + wn * 64 + nt * 8 + 2 * l4;
                const float b0v = __ldg(bias + c);
                const float b1v = __ldg(bias + c + 1);
                float v00 = acc[mt][nt][0] + b0v, v01 = acc[mt][nt][1] + b1v;
                float v10 = acc[mt][nt][2] + b0v, v11 = acc[mt][nt][3] + b1v;
                const int sec = c >> 10;
                const int cs = c & 1023, h = cs >> 6, d0 = cs & 63;
                const int b  = row >> 11;
                const int t0 = row & 2047;
                const int t1 = (row + 8) & 2047;
                if (sec == 2) {
                    __half* vb = g_v + ((size_t)(b * HH + h) * HD) * TT;
                    vb[(size_t)d0 * TT + t0]       = __float2half_rn(v00);
                    vb[(size_t)(d0 + 1) * TT + t0] = __float2half_rn(v01);
                    vb[(size_t)d0 * TT + t1]       = __float2half_rn(v10);
                    vb[(size_t)(d0 + 1) * TT + t1] = __float2half_rn(v11);
                } else {
                    if (sec == 0) { v00 *= QS; v01 *= QS; v10 *= QS; v11 *= QS; }
                    __half* basep = (sec == 0) ? g_q : g_k;
                    __half* p0 = basep + (((size_t)(b * HH + h) * TT + t0) * HD + d0);
                    __half* p1 = basep + (((size_t)(b * HH + h) * TT + t1) * HD + d0);
                    *(uint32_t*)p0 = pack_h2(v00, v01);
                    *(uint32_t*)p1 = pack_h2(v10, v11);
                }
            }
        }
        __syncthreads();
        __threadfence();
        if (tid == 0) atomicAdd(&g_fq[mblock], 1);
        return;
    }

    if (bid >= 1280) {
        // ================= Proj GEMM (consumes g_fy, heavy-first) ===========
        const int pbid = bid - 1280;
        const int wid = tid >> 5;
        const int wm  = wid & 1;
        const int wn  = wid >> 1;
        const int rank = pbid >> 3, nblk = pbid & 7;
        const int mb_w = 15 - (rank >> 1);
        const int b    = rank & 1;
        const int mblock = b * 16 + mb_w;
        const int m0 = mblock << 7, n0 = nblk << 7;

        if (tid == 0) {
            spin_flag(g_fy, mblock, 16);
            __threadfence();
        }
        __syncthreads();

        float acc[4][8][4];
#pragma unroll
        for (int mt = 0; mt < 4; mt++)
#pragma unroll
            for (int nt = 0; nt < 8; nt++)
#pragma unroll
                for (int j = 0; j < 4; j++) acc[mt][nt][j] = 0.0f;

        gemm_mainloop(sbase, Yg + (size_t)m0 * CC, Wp + (size_t)n0 * CC,
                      tid, wm, wn, lane, acc);

#pragma unroll
        for (int mt = 0; mt < 4; mt++) {
#pragma unroll
            for (int nt = 0; nt < 8; nt++) {
                const int row = m0 + wm * 64 + mt * 16 + r;
                const int c   = n0 + wn * 64 + nt * 8 + 2 * l4;
                const float b0v = __ldg(bp + c);
                const float b1v = __ldg(bp + c + 1);
                *(float2*)(Out + (size_t)row * CC + c)
                    = make_float2(acc[mt][nt][0] + b0v, acc[mt][nt][1] + b1v);
                *(float2*)(Out + (size_t)(row + 8) * CC + c)
                    = make_float2(acc[mt][nt][2] + b0v, acc[mt][nt][3] + b1v);
            }
        }
        return;
    }

    // === Flash attention: q-tile 128, 4 warps (32 q-rows each), desc k ====
    {
        const int abid = bid - 768;                 // 0..511
        const int qb   = 15 - (abid >> 5);          // heavy-first, 0..15
        const int bh   = abid & 31;
        const int b    = bh >> 4, h = bh & 15;
        const int qbase = qb * 128;
        const int bqoff  = b * 16;
        const int w = tid >> 5;

        const uint32_t koff = (uint32_t)AT_BUF;
        const uint32_t PS_B = (uint32_t)(4 * 64 * AT_STR * 2);   // Ps: 128 rows

        const __half* Qp  = g_q + (size_t)bh * TT * HD;
        const __half* Kp  = g_k + (size_t)bh * TT * HD;
        const __half* Vtp = g_v + (size_t)bh * HD * TT;

        // Q (m-block qb) and first two k-tiles (2qb+1, 2qb) are in block qb
        if (tid == 0) {
            spin_flag(g_fq, bqoff + qb, 24);
            __threadfence();
        }
        __syncthreads();

        const int ktop = 2 * qb + 1;                // first (descending) k-tile
        // Q (128x64) into Ps; K/V tile ktop into buffer (ktop & 1)
        {
            const int kb0 = ktop * 64;
            const uint32_t buf0 = (uint32_t)(ktop & 1);
#pragma unroll
            for (int i = 0; i < 8; i++) {
                int f = tid + i * 128;              // 0..1023
                int row = f >> 3, c = f & 7;
                cp_async16(sbase + PS_B + (uint32_t)(row * AT_STR) * 2 + c * 16,
                           Qp + (size_t)(qbase + row) * HD + c * 8);
            }
#pragma unroll
            for (int i = 0; i < 4; i++) {
                int f = tid + i * 128;              // 0..511
                int row = f >> 3, c = f & 7;
                cp_async16(sbase + buf0 * koff + (uint32_t)(row * AT_STR) * 2 + c * 16,
                           Kp + (size_t)(kb0 + row) * HD + c * 8);
                cp_async16(sbase + 2 * koff + buf0 * koff
                           + (uint32_t)(row * AT_STR) * 2 + c * 16,
                           Vtp + (size_t)row * TT + kb0 + c * 8);
            }
        }
        asm volatile("cp.async.commit_group;" ::: "memory");
        asm volatile("cp.async.wait_group 0;" ::: "memory");
        __syncthreads();

        const int aRowL = lane & 15;
        const int aColL = ((lane >> 4) & 1) * 8;
        const int bRowL = ((lane >> 4) << 3) + (lane & 7);
        const int bColL = ((lane >> 3) & 1) * 8;

        // Q fragments: 2 q-subtiles x 4 chunks
        uint32_t aq[2][4][4];
#pragma unroll
        for (int mt = 0; mt < 2; mt++)
#pragma unroll
            for (int hc = 0; hc < 4; hc++)
                ldsm4(aq[mt][hc], sbase + PS_B +
                      (uint32_t)(((w * 32 + mt * 16 + aRowL) * AT_STR
                                  + hc * 16 + aColL) * 2));
        __syncthreads();   // Ps now free for P

        float O[2][8][4];
#pragma unroll
        for (int mt = 0; mt < 2; mt++)
#pragma unroll
            for (int nt = 0; nt < 8; nt++)
#pragma unroll
                for (int j = 0; j < 4; j++) O[mt][nt][j] = 0.0f;
        float mv[2][2], lv[2][2];
#pragma unroll
        for (int mt = 0; mt < 2; mt++) {
            mv[mt][0] = -1e30f; mv[mt][1] = -1e30f;
            lv[mt][0] = 0.0f;   lv[mt][1] = 0.0f;
        }

        __half* pw = smh + 4 * 64 * AT_STR + (w * 32) * AT_STR;
        const uint32_t pwAddr = sbase + PS_B + (uint32_t)(w * 32 * AT_STR * 2);

        for (int kt = ktop; kt >= 0; kt--) {
            const int kbase = kt * 64;
            const int buf = kt & 1;
            const uint32_t kAddr = sbase + (uint32_t)buf * koff;
            const uint32_t vAddr = sbase + 2 * koff + (uint32_t)buf * koff;
            const bool more = (kt > 0);

            if (more) {
                const int nb = kbase - 64;
                uint32_t kd = sbase + (uint32_t)(buf ^ 1) * koff;
                uint32_t vd = sbase + 2 * koff + (uint32_t)(buf ^ 1) * koff;
#pragma unroll
                for (int i = 0; i < 4; i++) {
                    int f = tid + i * 128;
                    int row = f >> 3, c = f & 7;
                    cp_async16(kd + (uint32_t)(row * AT_STR) * 2 + c * 16,
                               Kp + (size_t)(nb + row) * HD + c * 8);
                    cp_async16(vd + (uint32_t)(row * AT_STR) * 2 + c * 16,
                               Vtp + (size_t)row * TT + nb + c * 8);
                }
                asm volatile("cp.async.commit_group;" ::: "memory");
            }

            // S = Q K^T  (2 q-subtiles share each K fragment)
            float s[2][8][4];
#pragma unroll
            for (int mt = 0; mt < 2; mt++)
#pragma unroll
                for (int nt = 0; nt < 8; nt++)
#pragma unroll
                    for (int j = 0; j < 4; j++) s[mt][nt][j] = 0.0f;
#pragma unroll
            for (int hc = 0; hc < 4; hc++) {
                uint32_t ku[4][4];
#pragma unroll
                for (int p = 0; p < 4; p++)
                    ldsm4(ku[p], kAddr + (uint32_t)(((p * 16 + bRowL) * AT_STR
                                                    + hc * 16 + bColL) * 2));
#pragma unroll
                for (int mt = 0; mt < 2; mt++)
#pragma unroll
                    for (int nt = 0; nt < 8; nt++)
                        mma_f16(s[mt][nt], aq[mt][hc][0], aq[mt][hc][1],
                                aq[mt][hc][2], aq[mt][hc][3],
                                ku[nt >> 1][(nt & 1) * 2],
                                ku[nt >> 1][(nt & 1) * 2 + 1]);
            }

            // causal mask (tiles near the diagonal of this warp's rows)
            if (kbase + 63 > qbase + w * 32) {
#pragma unroll
                for (int mt = 0; mt < 2; mt++) {
                    const int tqa = qbase + w * 32 + mt * 16 + r;
                    const int tqb = tqa + 8;
#pragma unroll
                    for (int nt = 0; nt < 8; nt++) {
                        int tk = kbase + nt * 8 + 2 * l4;
                        if (tk     > tqa) s[mt][nt][0] = -1e30f;
                        if (tk + 1 > tqa) s[mt][nt][1] = -1e30f;
                        if (tk     > tqb) s[mt][nt][2] = -1e30f;
                        if (tk + 1 > tqb) s[mt][nt][3] = -1e30f;
                    }
                }
            }

            // online softmax (log2 domain), per q-subtile
#pragma unroll
            for (int mt = 0; mt < 2; mt++) {
                float ml0 = -1e30f, ml1 = -1e30f;
#pragma unroll
                for (int nt = 0; nt < 8; nt++) {
                    ml0 = fmaxf(ml0, fmaxf(s[mt][nt][0], s[mt][nt][1]));
                    ml1 = fmaxf(ml1, fmaxf(s[mt][nt][2], s[mt][nt][3]));
                }
                ml0 = fmaxf(ml0, __shfl_xor_sync(0xffffffffu, ml0, 1));
                ml0 = fmaxf(ml0, __shfl_xor_sync(0xffffffffu, ml0, 2));
                ml1 = fmaxf(ml1, __shfl_xor_sync(0xffffffffu, ml1, 1));
                ml1 = fmaxf(ml1, __shfl_xor_sync(0xffffffffu, ml1, 2));
                float mn0 = fmaxf(mv[mt][0], ml0), mn1 = fmaxf(mv[mt][1], ml1);
                float c0 = ex2(mv[mt][0] - mn0), c1 = ex2(mv[mt][1] - mn1);
                float ps0 = 0.0f, ps1 = 0.0f;
#pragma unroll
                for (int nt = 0; nt < 8; nt++) {
                    s[mt][nt][0] = ex2(s[mt][nt][0] - mn0); ps0 += s[mt][nt][0];
                    s[mt][nt][1] = ex2(s[mt][nt][1] - mn0); ps0 += s[mt][nt][1];
                    s[mt][nt][2] = ex2(s[mt][nt][2] - mn1); ps1 += s[mt][nt][2];
                    s[mt][nt][3] = ex2(s[mt][nt][3] - mn1); ps1 += s[mt][nt][3];
                }
                ps0 += __shfl_xor_sync(0xffffffffu, ps0, 1);
                ps0 += __shfl_xor_sync(0xffffffffu, ps0, 2);
                ps1 += __shfl_xor_sync(0xffffffffu, ps1, 1);
                ps1 += __shfl_xor_sync(0xffffffffu, ps1, 2);
                lv[mt][0] = lv[mt][0] * c0 + ps0; mv[mt][0] = mn0;
                lv[mt][1] = lv[mt][1] * c1 + ps1; mv[mt][1] = mn1;
#pragma unroll
                for (int nt = 0; nt < 8; nt++) {
                    O[mt][nt][0] *= c0; O[mt][nt][1] *= c0;
                    O[mt][nt][2] *= c1; O[mt][nt][3] *= c1;
                }
            }

            // P -> per-warp smem as half2 (32 rows)
#pragma unroll
            for (int mt = 0; mt < 2; mt++)
#pragma unroll
                for (int nt = 0; nt < 8; nt++) {
                    *(uint32_t*)(pw + (mt * 16 + r) * AT_STR + nt * 8 + 2 * l4)
                        = pack_h2(s[mt][nt][0], s[mt][nt][1]);
                    *(uint32_t*)(pw + (mt * 16 + r + 8) * AT_STR + nt * 8 + 2 * l4)
                        = pack_h2(s[mt][nt][2], s[mt][nt][3]);
                }
            __syncwarp();

            // O += P V (V fragments shared across both q-subtiles)
#pragma unroll
            for (int hc = 0; hc < 4; hc++) {
                uint32_t pa[2][4];
#pragma unroll
                for (int mt = 0; mt < 2; mt++)
                    ldsm4(pa[mt], pwAddr + (uint32_t)(((mt * 16 + aRowL) * AT_STR
                                                      + hc * 16 + aColL) * 2));
                uint32_t vu[4][4];
#pragma unroll
                for (int p = 0; p < 4; p++)
                    ldsm4(vu[p], vAddr + (uint32_t)(((p * 16 + bRowL) * AT_STR
                                                    + hc * 16 + bColL) * 2));
#pragma unroll
                for (int mt = 0; mt < 2; mt++)
#pragma unroll
                    for (int nt = 0; nt < 8; nt++)
                        mma_f16(O[mt][nt], pa[mt][0], pa[mt][1], pa[mt][2],
                                pa[mt][3], vu[nt >> 1][(nt & 1) * 2],
                                vu[nt >> 1][(nt & 1) * 2 + 1]);
            }

            if (more) {
                asm volatile("cp.async.wait_group 0;" ::: "memory");
                if (tid == 0) {
                    if (kt - 2 >= 0) spin_flag(g_fq, bqoff + ((kt - 2) >> 1), 24);
                    __threadfence();
                }
                __syncthreads();
            }
        }

        // Epilogue: normalize, half y, release g_fy
        const int hb = h * 64;
#pragma unroll
        for (int mt = 0; mt < 2; mt++) {
            const int tqa = qbase + w * 32 + mt * 16 + r;
            const float inv0 = 1.0f / lv[mt][0], inv1 = 1.0f / lv[mt][1];
            __half* y0 = Yg + (size_t)(b * TT + tqa) * CC;
            __half* y1 = Yg + (size_t)(b * TT + tqa + 8) * CC;
#pragma unroll
            for (int nt = 0; nt < 8; nt++) {
                int c = hb + nt * 8 + 2 * l4;
                *(uint32_t*)(y0 + c) = pack_h2(O[mt][nt][0] * inv0,
                                               O[mt][nt][1] * inv0);
                *(uint32_t*)(y1 + c) = pack_h2(O[mt][nt][2] * inv1,
                                               O[mt][nt][3] * inv1);
            }
        }
        __syncthreads();
        __threadfence();
        if (tid == 0) atomicAdd(&g_fy[b * 16 + qb], 1);
    }
}

// ---------------------------------------------------------------------------
// Launch
// ---------------------------------------------------------------------------
extern "C" void kernel_launch(void* const* d_in, const int* in_sizes, int n_in,
                              void* d_out, int out_size)
{
    const float* x     = (const float*)d_in[0];
    const float* Wqkv  = (const float*)d_in[1];
    const float* bqkv  = (const float*)d_in[2];
    const float* Wproj = (const float*)d_in[3];
    const float* bproj = (const float*)d_in[4];
    float* out = (float*)d_out;
    (void)in_sizes; (void)n_in; (void)out_size;

    __half *yp, *xp, *wtq, *wtp;
    cudaGetSymbolAddress((void**)&yp,  g_y);
    cudaGetSymbolAddress((void**)&xp,  g_xp);
    cudaGetSymbolAddress((void**)&wtq, g_wtq);
    cudaGetSymbolAddress((void**)&wtp, g_wtp);

    cudaFuncSetAttribute(mega_kernel, cudaFuncAttributeMaxDynamicSharedMemorySize, GEMM_SMEM);

    prep_all<<<4096 + 3072 + 1024, 256>>>(x, Wqkv, Wproj, xp, wtq, wtp);

    mega_kernel<<<768 + 512 + 256, 128, GEMM_SMEM>>>(xp, wtq, bqkv, yp,
                                                     wtp, bproj, out);
}

// round 16
// speedup vs baseline: 1.1652x; 1.0393x over previous
#include <cuda_runtime.h>
#include <cuda_fp16.h>
#include <math.h>
#include <stdint.h>

#define BB   2
#define TT   2048
#define CC   1024
#define HH   16
#define HD   64
#define MROWS (BB*TT)        // 4096
#define N_QKV (3*CC)         // 3072

// ---------------------------------------------------------------------------
// Scratch (device globals) — fp16
// ---------------------------------------------------------------------------
__device__ __align__(1024) __half g_q[BB*HH*TT*HD];   // [B,H,T,HD], pre-scaled by 0.125*log2e
__device__ __align__(1024) __half g_k[BB*HH*TT*HD];   // [B,H,T,HD]
__device__ __align__(1024) __half g_v[BB*HH*TT*HD];   // [B,H,HD,T]  (TRANSPOSED)
__device__ __align__(1024) __half g_y[MROWS*CC];      // attn out
__device__ __align__(1024) __half g_xp[MROWS*CC];     // x
__device__ __align__(1024) __half g_wtq[N_QKV*CC];    // Wqkv^T
__device__ __align__(1024) __half g_wtp[CC*CC];       // Wproj^T
__device__ int g_fq[32];                              // per-m-block QKV flags
__device__ int g_fy[32];                              // per-m-block attn-out flags

// ---------------------------------------------------------------------------
// Helpers
// ---------------------------------------------------------------------------
__device__ __forceinline__ float ex2(float x) {
    float r;
    asm("ex2.approx.f32 %0, %1;" : "=f"(r) : "f"(x));
    return r;
}

__device__ __forceinline__ uint32_t pack_h2(float lo, float hi) {
    uint32_t r;
    asm("cvt.rn.f16x2.f32 %0, %1, %2;" : "=r"(r) : "f"(hi), "f"(lo));
    return r;
}

__device__ __forceinline__ uint32_t s2u(const void* p) {
    uint32_t a;
    asm("{ .reg .u64 t; cvta.to.shared.u64 t, %1; cvt.u32.u64 %0, t; }"
        : "=r"(a) : "l"(p));
    return a;
}

__device__ __forceinline__ void cp_async16(uint32_t dst, const void* src) {
    asm volatile("cp.async.cg.shared.global [%0], [%1], 16;"
                 :: "r"(dst), "l"(src) : "memory");
}

__device__ __forceinline__ void ldsm4(uint32_t r[4], uint32_t addr) {
    asm volatile("ldmatrix.sync.aligned.m8n8.x4.shared.b16 {%0,%1,%2,%3}, [%4];"
                 : "=r"(r[0]), "=r"(r[1]), "=r"(r[2]), "=r"(r[3]) : "r"(addr));
}

__device__ __forceinline__ void mma_f16(float d[4], uint32_t a0, uint32_t a1,
                                        uint32_t a2, uint32_t a3,
                                        uint32_t b0, uint32_t b1)
{
    asm volatile(
        "mma.sync.aligned.m16n8k16.row.col.f32.f16.f16.f32 "
        "{%0,%1,%2,%3}, {%4,%5,%6,%7}, {%8,%9}, {%0,%1,%2,%3};"
        : "+f"(d[0]), "+f"(d[1]), "+f"(d[2]), "+f"(d[3])
        : "r"(a0), "r"(a1), "r"(a2), "r"(a3), "r"(b0), "r"(b1));
}

__device__ __forceinline__ void spin_flag(int* flags, int idx, int target) {
    while (*((volatile int*)&flags[idx]) < target) __nanosleep(64);
}

// ---------------------------------------------------------------------------
// Combined prep kernel (one launch)
// ---------------------------------------------------------------------------
__global__ void prep_all(const float* __restrict__ x,
                         const float* __restrict__ Wqkv,
                         const float* __restrict__ Wproj,
                         __half* __restrict__ xp,
                         __half* __restrict__ wtq,
                         __half* __restrict__ wtp)
{
    const int bid = blockIdx.x;
    const int tid = threadIdx.x;
    if (bid == 0 && tid < 64) {
        if (tid < 32) g_fq[tid] = 0;
        else          g_fy[tid - 32] = 0;
    }
    if (bid < 4096) {
        int i = bid * 256 + tid;
        float4 v = ((const float4*)x)[i];
        uint2 o;
        o.x = pack_h2(v.x, v.y);
        o.y = pack_h2(v.z, v.w);
        ((uint2*)xp)[i] = o;
        return;
    }
    __shared__ float t[32][33];
    const float* in;
    __half* out;
    int R, C, bx, by;
    if (bid < 4096 + 3072) {
        int tb = bid - 4096;
        in = Wqkv; out = wtq; R = CC; C = N_QKV;
        bx = tb % 96; by = tb / 96;
    } else {
        int tb = bid - 4096 - 3072;
        in = Wproj; out = wtp; R = CC; C = CC;
        bx = tb & 31; by = tb >> 5;
    }
    int xx = tid & 31, yy = tid >> 5;
    int c0 = bx * 32, r0 = by * 32;
#pragma unroll
    for (int i = 0; i < 32; i += 8)
        t[yy + i][xx] = in[(size_t)(r0 + yy + i) * C + c0 + xx];
    __syncthreads();
#pragma unroll
    for (int i = 0; i < 32; i += 8)
        out[(size_t)(c0 + yy + i) * R + r0 + xx] = __float2half_rn(t[xx][yy + i]);
}

// ---------------------------------------------------------------------------
// GEMM tiling: CTA 128x128, 256 threads (8 warps, 4Mx2N, warp 32x64),
// K-block 64, 3-stage cp.async, 2 CTAs/SM (16 warps/SM).
// ---------------------------------------------------------------------------
#define GSTAGES 3
#define KB      64
#define HSTR    72
#define TILEH   (128*HSTR)
#define TILE_B  (TILEH*2)
#define GEMM_SMEM (GSTAGES*2*TILE_B)

#define AT_STR  72
#define AT_BUF  (64*AT_STR*2)

__device__ __forceinline__ void g_load_stage(uint32_t sbase, int s,
                                             const __half* Ag, const __half* Bg,
                                             int k0, int tid)
{
    uint32_t base = sbase + (uint32_t)s * 2 * TILE_B;
#pragma unroll
    for (int i = 0; i < 4; i++) {
        int f = tid + i * 256;          // 0..1023
        int row = f >> 3, c = f & 7;
        cp_async16(base + row * (HSTR * 2) + c * 16,
                   Ag + (size_t)row * CC + k0 + c * 8);
        cp_async16(base + TILE_B + row * (HSTR * 2) + c * 16,
                   Bg + (size_t)row * CC + k0 + c * 8);
    }
    asm volatile("cp.async.commit_group;" ::: "memory");
}

// Shared fp16 GEMM mainloop: warp tile 32x64, acc[2][8][4]
__device__ __forceinline__ void gemm_mainloop(uint32_t sbase,
                                              const __half* Ag, const __half* Bg,
                                              int tid, int wm, int wn, int lane,
                                              float acc[2][8][4])
{
    const int aRow = wm * 32 + (lane & 15);
    const int aCol = ((lane >> 4) & 1) * 8;
    const int bRow = wn * 64 + ((lane >> 4) << 3) + (lane & 7);
    const int bCol = ((lane >> 3) & 1) * 8;

    const int NIT = CC / KB;   // 16
#pragma unroll
    for (int s = 0; s < GSTAGES - 1; s++)
        g_load_stage(sbase, s, Ag, Bg, s * KB, tid);

    for (int it = 0; it < NIT; it++) {
        if (it < NIT - 1)
            asm volatile("cp.async.wait_group %0;" :: "n"(GSTAGES - 2) : "memory");
        else
            asm volatile("cp.async.wait_group 0;" ::: "memory");
        __syncthreads();

        if (it + GSTAGES - 1 < NIT)
            g_load_stage(sbase, (it + GSTAGES - 1) % GSTAGES, Ag, Bg,
                         (it + GSTAGES - 1) * KB, tid);

        const uint32_t Aab = sbase + (uint32_t)(it % GSTAGES) * 2 * TILE_B;
        const uint32_t Bab = Aab + TILE_B;

#pragma unroll
        for (int h = 0; h < 4; h++) {
            uint32_t au[2][4];
#pragma unroll
            for (int mt = 0; mt < 2; mt++)
                ldsm4(au[mt], Aab + (uint32_t)(((aRow + mt * 16) * HSTR
                                                + h * 16 + aCol) * 2));
            uint32_t bu[4][4];
#pragma unroll
            for (int p = 0; p < 4; p++)
                ldsm4(bu[p], Bab + (uint32_t)(((bRow + p * 16) * HSTR
                                               + h * 16 + bCol) * 2));
#pragma unroll
            for (int mt = 0; mt < 2; mt++)
#pragma unroll
                for (int nt = 0; nt < 8; nt++)
                    mma_f16(acc[mt][nt], au[mt][0], au[mt][1], au[mt][2],
                            au[mt][3], bu[nt >> 1][(nt & 1) * 2],
                            bu[nt >> 1][(nt & 1) * 2 + 1]);
        }
    }
}

// ---------------------------------------------------------------------------
// Mega-kernel (256 threads/CTA):
//   bids    0.. 767 : QKV GEMM, DESCENDING-t m-blocks (release g_fq)
//   bids  768..1279 : flash attention, q-tile 128, 8 warps, DESC k-tiles
//   bids 1280..1535 : proj GEMM heavy-first (consume g_fy, target 16)
// ---------------------------------------------------------------------------
__global__ __launch_bounds__(256, 2)
void mega_kernel(const __half* __restrict__ A, const __half* __restrict__ Bt,
                 const float* __restrict__ bias, __half* __restrict__ Yg,
                 const __half* __restrict__ Wp, const float* __restrict__ bp,
                 float* __restrict__ Out)
{
    extern __shared__ __align__(16) __half smh[];
    const uint32_t sbase = s2u(smh);
    const int tid = threadIdx.x;
    const int bid = blockIdx.x;
    const int lane = tid & 31;
    const int r    = lane >> 2;
    const int l4   = lane & 3;

    if (bid < 768) {
        // ================= QKV GEMM (descending-t production) ==============
        const int wid = tid >> 5;
        const int wm  = wid & 3;            // 4 along M
        const int wn  = wid >> 2;           // 2 along N
        const int rank = bid / 24, nblk = bid % 24;
        const int mblock = ((rank & 1) << 4) | (15 - (rank >> 1));
        const int m0 = mblock << 7, n0 = nblk << 7;

        float acc[2][8][4];
#pragma unroll
        for (int mt = 0; mt < 2; mt++)
#pragma unroll
            for (int nt = 0; nt < 8; nt++)
#pragma unroll
                for (int j = 0; j < 4; j++) acc[mt][nt][j] = 0.0f;

        gemm_mainloop(sbase, A + (size_t)m0 * CC, Bt + (size_t)n0 * CC,
                      tid, wm, wn, lane, acc);

        const float QS = 0.125f * 1.44269504089f;
#pragma unroll
        for (int mt = 0; mt < 2; mt++) {
#pragma unroll
            for (int nt = 0; nt < 8; nt++) {
                const int row = m0 + wm * 32 + mt * 16 + r;
                const int c   = n0 + wn * 64 + nt * 8 + 2 * l4;
                const float b0v = __ldg(bias + c);
                const float b1v = __ldg(bias + c + 1);
                float v00 = acc[mt][nt][0] + b0v, v01 = acc[mt][nt][1] + b1v;
                float v10 = acc[mt][nt][2] + b0v, v11 = acc[mt][nt][3] + b1v;
                const int sec = c >> 10;
                const int cs = c & 1023, h = cs >> 6, d0 = cs & 63;
                const int b  = row >> 11;
                const int t0 = row & 2047;
                const int t1 = (row + 8) & 2047;
                if (sec == 2) {
                    __half* vb = g_v + ((size_t)(b * HH + h) * HD) * TT;
                    vb[(size_t)d0 * TT + t0]       = __float2half_rn(v00);
                    vb[(size_t)(d0 + 1) * TT + t0] = __float2half_rn(v01);
                    vb[(size_t)d0 * TT + t1]       = __float2half_rn(v10);
                    vb[(size_t)(d0 + 1) * TT + t1] = __float2half_rn(v11);
                } else {
                    if (sec == 0) { v00 *= QS; v01 *= QS; v10 *= QS; v11 *= QS; }
                    __half* basep = (sec == 0) ? g_q : g_k;
                    __half* p0 = basep + (((size_t)(b * HH + h) * TT + t0) * HD + d0);
                    __half* p1 = basep + (((size_t)(b * HH + h) * TT + t1) * HD + d0);
                    *(uint32_t*)p0 = pack_h2(v00, v01);
                    *(uint32_t*)p1 = pack_h2(v10, v11);
                }
            }
        }
        __syncthreads();
        __threadfence();
        if (tid == 0) atomicAdd(&g_fq[mblock], 1);
        return;
    }

    if (bid >= 1280) {
        // ================= Proj GEMM (consumes g_fy, heavy-first) ===========
        const int pbid = bid - 1280;
        const int wid = tid >> 5;
        const int wm  = wid & 3;
        const int wn  = wid >> 2;
        const int rank = pbid >> 3, nblk = pbid & 7;
        const int mb_w = 15 - (rank >> 1);
        const int b    = rank & 1;
        const int mblock = b * 16 + mb_w;
        const int m0 = mblock << 7, n0 = nblk << 7;

        if (tid == 0) {
            spin_flag(g_fy, mblock, 16);
            __threadfence();
        }
        __syncthreads();

        float acc[2][8][4];
#pragma unroll
        for (int mt = 0; mt < 2; mt++)
#pragma unroll
            for (int nt = 0; nt < 8; nt++)
#pragma unroll
                for (int j = 0; j < 4; j++) acc[mt][nt][j] = 0.0f;

        gemm_mainloop(sbase, Yg + (size_t)m0 * CC, Wp + (size_t)n0 * CC,
                      tid, wm, wn, lane, acc);

#pragma unroll
        for (int mt = 0; mt < 2; mt++) {
#pragma unroll
            for (int nt = 0; nt < 8; nt++) {
                const int row = m0 + wm * 32 + mt * 16 + r;
                const int c   = n0 + wn * 64 + nt * 8 + 2 * l4;
                const float b0v = __ldg(bp + c);
                const float b1v = __ldg(bp + c + 1);
                *(float2*)(Out + (size_t)row * CC + c)
                    = make_float2(acc[mt][nt][0] + b0v, acc[mt][nt][1] + b1v);
                *(float2*)(Out + (size_t)(row + 8) * CC + c)
                    = make_float2(acc[mt][nt][2] + b0v, acc[mt][nt][3] + b1v);
            }
        }
        return;
    }

    // === Flash attention: q-tile 128, 8 warps (16 q-rows each), desc k ====
    {
        const int abid = bid - 768;                 // 0..511
        const int qb   = 15 - (abid >> 5);          // heavy-first, 0..15
        const int bh   = abid & 31;
        const int b    = bh >> 4, h = bh & 15;
        const int qbase = qb * 128;
        const int bqoff  = b * 16;
        const int w = tid >> 5;                     // 0..7

        const uint32_t koff = (uint32_t)AT_BUF;
        const uint32_t PS_B = (uint32_t)(4 * 64 * AT_STR * 2);   // Ps: 128 rows

        const __half* Qp  = g_q + (size_t)bh * TT * HD;
        const __half* Kp  = g_k + (size_t)bh * TT * HD;
        const __half* Vtp = g_v + (size_t)bh * HD * TT;

        if (tid == 0) {
            spin_flag(g_fq, bqoff + qb, 24);
            __threadfence();
        }
        __syncthreads();

        const int ktop = 2 * qb + 1;                // first (descending) k-tile
        // Q (128x64) into Ps; K/V tile ktop into buffer (ktop & 1)
        {
            const int kb0 = ktop * 64;
            const uint32_t buf0 = (uint32_t)(ktop & 1);
#pragma unroll
            for (int i = 0; i < 4; i++) {
                int f = tid + i * 256;              // 0..1023
                int row = f >> 3, c = f & 7;
                cp_async16(sbase + PS_B + (uint32_t)(row * AT_STR) * 2 + c * 16,
                           Qp + (size_t)(qbase + row) * HD + c * 8);
            }
#pragma unroll
            for (int i = 0; i < 2; i++) {
                int f = tid + i * 256;              // 0..511
                int row = f >> 3, c = f & 7;
                cp_async16(sbase + buf0 * koff + (uint32_t)(row * AT_STR) * 2 + c * 16,
                           Kp + (size_t)(kb0 + row) * HD + c * 8);
                cp_async16(sbase + 2 * koff + buf0 * koff
                           + (uint32_t)(row * AT_STR) * 2 + c * 16,
                           Vtp + (size_t)row * TT + kb0 + c * 8);
            }
        }
        asm volatile("cp.async.commit_group;" ::: "memory");
        asm volatile("cp.async.wait_group 0;" ::: "memory");
        __syncthreads();

        const int aRowL = lane & 15;
        const int aColL = ((lane >> 4) & 1) * 8;
        const int bRowL = ((lane >> 4) << 3) + (lane & 7);
        const int bColL = ((lane >> 3) & 1) * 8;

        uint32_t aq[4][4];
#pragma unroll
        for (int hc = 0; hc < 4; hc++)
            ldsm4(aq[hc], sbase + PS_B +
                  (uint32_t)(((w * 16 + aRowL) * AT_STR + hc * 16 + aColL) * 2));
        __syncthreads();   // Ps now free for P

        float O[8][4];
#pragma unroll
        for (int nt = 0; nt < 8; nt++)
#pragma unroll
            for (int j = 0; j < 4; j++) O[nt][j] = 0.0f;
        float m0v = -1e30f, m1v = -1e30f, l0v = 0.0f, l1v = 0.0f;

        const int tq0 = qbase + w * 16 + r;
        const int tq1 = tq0 + 8;
        __half* pw = smh + 4 * 64 * AT_STR + (w * 16) * AT_STR;
        const uint32_t pwAddr = sbase + PS_B + (uint32_t)(w * 16 * AT_STR * 2);

        for (int kt = ktop; kt >= 0; kt--) {
            const int kbase = kt * 64;
            const int buf = kt & 1;
            const uint32_t kAddr = sbase + (uint32_t)buf * koff;
            const uint32_t vAddr = sbase + 2 * koff + (uint32_t)buf * koff;
            const bool more = (kt > 0);

            if (more) {
                const int nb = kbase - 64;
                uint32_t kd = sbase + (uint32_t)(buf ^ 1) * koff;
                uint32_t vd = sbase + 2 * koff + (uint32_t)(buf ^ 1) * koff;
#pragma unroll
                for (int i = 0; i < 2; i++) {
                    int f = tid + i * 256;
                    int row = f >> 3, c = f & 7;
                    cp_async16(kd + (uint32_t)(row * AT_STR) * 2 + c * 16,
                               Kp + (size_t)(nb + row) * HD + c * 8);
                    cp_async16(vd + (uint32_t)(row * AT_STR) * 2 + c * 16,
                               Vtp + (size_t)row * TT + nb + c * 8);
                }
                asm volatile("cp.async.commit_group;" ::: "memory");
            }

            // S = Q K^T
            float s[8][4];
#pragma unroll
            for (int nt = 0; nt < 8; nt++)
#pragma unroll
                for (int j = 0; j < 4; j++) s[nt][j] = 0.0f;
#pragma unroll
            for (int hc = 0; hc < 4; hc++) {
                uint32_t ku[4][4];
#pragma unroll
                for (int p = 0; p < 4; p++)
                    ldsm4(ku[p], kAddr + (uint32_t)(((p * 16 + bRowL) * AT_STR
                                                    + hc * 16 + bColL) * 2));
#pragma unroll
                for (int nt = 0; nt < 8; nt++)
                    mma_f16(s[nt], aq[hc][0], aq[hc][1], aq[hc][2], aq[hc][3],
                            ku[nt >> 1][(nt & 1) * 2],
                            ku[nt >> 1][(nt & 1) * 2 + 1]);
            }

            // causal mask (diagonal region only)
            if (kbase + 63 > qbase + w * 16) {
#pragma unroll
                for (int nt = 0; nt < 8; nt++) {
                    int tk = kbase + nt * 8 + 2 * l4;
                    if (tk     > tq0) s[nt][0] = -1e30f;
                    if (tk + 1 > tq0) s[nt][1] = -1e30f;
                    if (tk     > tq1) s[nt][2] = -1e30f;
                    if (tk + 1 > tq1) s[nt][3] = -1e30f;
                }
            }

            // online softmax (log2 domain)
            float ml0 = -1e30f, ml1 = -1e30f;
#pragma unroll
            for (int nt = 0; nt < 8; nt++) {
                ml0 = fmaxf(ml0, fmaxf(s[nt][0], s[nt][1]));
                ml1 = fmaxf(ml1, fmaxf(s[nt][2], s[nt][3]));
            }
            ml0 = fmaxf(ml0, __shfl_xor_sync(0xffffffffu, ml0, 1));
            ml0 = fmaxf(ml0, __shfl_xor_sync(0xffffffffu, ml0, 2));
            ml1 = fmaxf(ml1, __shfl_xor_sync(0xffffffffu, ml1, 1));
            ml1 = fmaxf(ml1, __shfl_xor_sync(0xffffffffu, ml1, 2));
            float mn0 = fmaxf(m0v, ml0), mn1 = fmaxf(m1v, ml1);
            float c0 = ex2(m0v - mn0), c1 = ex2(m1v - mn1);
            float ps0 = 0.0f, ps1 = 0.0f;
#pragma unroll
            for (int nt = 0; nt < 8; nt++) {
                s[nt][0] = ex2(s[nt][0] - mn0); ps0 += s[nt][0];
                s[nt][1] = ex2(s[nt][1] - mn0); ps0 += s[nt][1];
                s[nt][2] = ex2(s[nt][2] - mn1); ps1 += s[nt][2];
                s[nt][3] = ex2(s[nt][3] - mn1); ps1 += s[nt][3];
            }
            ps0 += __shfl_xor_sync(0xffffffffu, ps0, 1);
            ps0 += __shfl_xor_sync(0xffffffffu, ps0, 2);
            ps1 += __shfl_xor_sync(0xffffffffu, ps1, 1);
            ps1 += __shfl_xor_sync(0xffffffffu, ps1, 2);
            l0v = l0v * c0 + ps0; m0v = mn0;
            l1v = l1v * c1 + ps1; m1v = mn1;
#pragma unroll
            for (int nt = 0; nt < 8; nt++) {
                O[nt][0] *= c0; O[nt][1] *= c0;
                O[nt][2] *= c1; O[nt][3] *= c1;
            }

            // P -> per-warp smem as half2
#pragma unroll
            for (int nt = 0; nt < 8; nt++) {
                *(uint32_t*)(pw + r * AT_STR + nt * 8 + 2 * l4)
                    = pack_h2(s[nt][0], s[nt][1]);
                *(uint32_t*)(pw + (r + 8) * AT_STR + nt * 8 + 2 * l4)
                    = pack_h2(s[nt][2], s[nt][3]);
            }
            __syncwarp();

            // O += P V
#pragma unroll
            for (int hc = 0; hc < 4; hc++) {
                uint32_t pa[4];
                ldsm4(pa, pwAddr + (uint32_t)((aRowL * AT_STR
                                               + hc * 16 + aColL) * 2));
                uint32_t vu[4][4];
#pragma unroll
                for (int p = 0; p < 4; p++)
                    ldsm4(vu[p], vAddr + (uint32_t)(((p * 16 + bRowL) * AT_STR
                                                    + hc * 16 + bColL) * 2));
#pragma unroll
                for (int nt = 0; nt < 8; nt++)
                    mma_f16(O[nt], pa[0], pa[1], pa[2], pa[3],
                            vu[nt >> 1][(nt & 1) * 2],
                            vu[nt >> 1][(nt & 1) * 2 + 1]);
            }

            if (more) {
                asm volatile("cp.async.wait_group 0;" ::: "memory");
                if (tid == 0) {
                    if (kt - 2 >= 0) spin_flag(g_fq, bqoff + ((kt - 2) >> 1), 24);
                    __threadfence();
                }
                __syncthreads();
            }
        }

        // Epilogue: normalize, half y, release g_fy
        const int hb = h * 64;
        const float inv0 = 1.0f / l0v, inv1 = 1.0f / l1v;
        __half* y0 = Yg + (size_t)(b * TT + tq0) * CC;
        __half* y1 = Yg + (size_t)(b * TT + tq1) * CC;
#pragma unroll
        for (int nt = 0; nt < 8; nt++) {
            int c = hb + nt * 8 + 2 * l4;
            *(uint32_t*)(y0 + c) = pack_h2(O[nt][0] * inv0, O[nt][1] * inv0);
            *(uint32_t*)(y1 + c) = pack_h2(O[nt][2] * inv1, O[nt][3] * inv1);
        }
        __syncthreads();
        __threadfence();
        if (tid == 0) atomicAdd(&g_fy[b * 16 + qb], 1);
    }
}

// ---------------------------------------------------------------------------
// Launch
// ---------------------------------------------------------------------------
extern "C" void kernel_launch(void* const* d_in, const int* in_sizes, int n_in,
                              void* d_out, int out_size)
{
    const float* x     = (const float*)d_in[0];
    const float* Wqkv  = (const float*)d_in[1];
    const float* bqkv  = (const float*)d_in[2];
    const float* Wproj = (const float*)d_in[3];
    const float* bproj = (const float*)d_in[4];
    float* out = (float*)d_out;
    (void)in_sizes; (void)n_in; (void)out_size;

    __half *yp, *xp, *wtq, *wtp;
    cudaGetSymbolAddress((void**)&yp,  g_y);
    cudaGetSymbolAddress((void**)&xp,  g_xp);
    cudaGetSymbolAddress((void**)&wtq, g_wtq);
    cudaGetSymbolAddress((void**)&wtp, g_wtp);

    cudaFuncSetAttribute(mega_kernel, cudaFuncAttributeMaxDynamicSharedMemorySize, GEMM_SMEM);

    prep_all<<<4096 + 3072 + 1024, 256>>>(x, Wqkv, Wproj, xp, wtq, wtp);

    mega_kernel<<<768 + 512 + 256, 256, GEMM_SMEM>>>(xp, wtq, bqkv, yp,
                                                     wtp, bproj, out);
}

// round 17
// speedup vs baseline: 1.2135x; 1.0414x over previous
#include <cuda_runtime.h>
#include <cuda_fp16.h>
#include <math.h>
#include <stdint.h>

#define BB   2
#define TT   2048
#define CC   1024
#define HH   16
#define HD   64
#define MROWS (BB*TT)        // 4096
#define N_QKV (3*CC)         // 3072

// ---------------------------------------------------------------------------
// Scratch (device globals) — fp16
// ---------------------------------------------------------------------------
__device__ __align__(1024) __half g_q[BB*HH*TT*HD];   // [B,H,T,HD], pre-scaled by 0.125*log2e
__device__ __align__(1024) __half g_k[BB*HH*TT*HD];   // [B,H,T,HD]
__device__ __align__(1024) __half g_v[BB*HH*TT*HD];   // [B,H,HD,T]  (TRANSPOSED)
__device__ __align__(1024) __half g_y[MROWS*CC];      // attn out
__device__ __align__(1024) __half g_xp[MROWS*CC];     // x
__device__ __align__(1024) __half g_wtq[N_QKV*CC];    // Wqkv^T
__device__ __align__(1024) __half g_wtp[CC*CC];       // Wproj^T
__device__ int g_fq[32];                              // per-m-block QKV flags
__device__ int g_fy[32];                              // per-m-block attn-out flags

// ---------------------------------------------------------------------------
// Helpers
// ---------------------------------------------------------------------------
__device__ __forceinline__ float ex2(float x) {
    float r;
    asm("ex2.approx.f32 %0, %1;" : "=f"(r) : "f"(x));
    return r;
}

__device__ __forceinline__ uint32_t pack_h2(float lo, float hi) {
    uint32_t r;
    asm("cvt.rn.f16x2.f32 %0, %1, %2;" : "=r"(r) : "f"(hi), "f"(lo));
    return r;
}

__device__ __forceinline__ uint32_t s2u(const void* p) {
    uint32_t a;
    asm("{ .reg .u64 t; cvta.to.shared.u64 t, %1; cvt.u32.u64 %0, t; }"
        : "=r"(a) : "l"(p));
    return a;
}

__device__ __forceinline__ void cp_async16(uint32_t dst, const void* src) {
    asm volatile("cp.async.cg.shared.global [%0], [%1], 16;"
                 :: "r"(dst), "l"(src) : "memory");
}

__device__ __forceinline__ void ldsm4(uint32_t r[4], uint32_t addr) {
    asm volatile("ldmatrix.sync.aligned.m8n8.x4.shared.b16 {%0,%1,%2,%3}, [%4];"
                 : "=r"(r[0]), "=r"(r[1]), "=r"(r[2]), "=r"(r[3]) : "r"(addr));
}

__device__ __forceinline__ void mma_f16(float d[4], uint32_t a0, uint32_t a1,
                                        uint32_t a2, uint32_t a3,
                                        uint32_t b0, uint32_t b1)
{
    asm volatile(
        "mma.sync.aligned.m16n8k16.row.col.f32.f16.f16.f32 "
        "{%0,%1,%2,%3}, {%4,%5,%6,%7}, {%8,%9}, {%0,%1,%2,%3};"
        : "+f"(d[0]), "+f"(d[1]), "+f"(d[2]), "+f"(d[3])
        : "r"(a0), "r"(a1), "r"(a2), "r"(a3), "r"(b0), "r"(b1));
}

__device__ __forceinline__ void spin_flag(int* flags, int idx, int target) {
    while (*((volatile int*)&flags[idx]) < target) __nanosleep(64);
}

// ---------------------------------------------------------------------------
// Combined prep kernel (one launch)
// ---------------------------------------------------------------------------
__global__ void prep_all(const float* __restrict__ x,
                         const float* __restrict__ Wqkv,
                         const float* __restrict__ Wproj,
                         __half* __restrict__ xp,
                         __half* __restrict__ wtq,
                         __half* __restrict__ wtp)
{
    const int bid = blockIdx.x;
    const int tid = threadIdx.x;
    if (bid == 0 && tid < 64) {
        if (tid < 32) g_fq[tid] = 0;
        else          g_fy[tid - 32] = 0;
    }
    if (bid < 4096) {
        int i = bid * 256 + tid;
        float4 v = ((const float4*)x)[i];
        uint2 o;
        o.x = pack_h2(v.x, v.y);
        o.y = pack_h2(v.z, v.w);
        ((uint2*)xp)[i] = o;
        return;
    }
    __shared__ float t[32][33];
    const float* in;
    __half* out;
    int R, C, bx, by;
    if (bid < 4096 + 3072) {
        int tb = bid - 4096;
        in = Wqkv; out = wtq; R = CC; C = N_QKV;
        bx = tb % 96; by = tb / 96;
    } else {
        int tb = bid - 4096 - 3072;
        in = Wproj; out = wtp; R = CC; C = CC;
        bx = tb & 31; by = tb >> 5;
    }
    int xx = tid & 31, yy = tid >> 5;
    int c0 = bx * 32, r0 = by * 32;
#pragma unroll
    for (int i = 0; i < 32; i += 8)
        t[yy + i][xx] = in[(size_t)(r0 + yy + i) * C + c0 + xx];
    __syncthreads();
#pragma unroll
    for (int i = 0; i < 32; i += 8)
        out[(size_t)(c0 + yy + i) * R + r0 + xx] = __float2half_rn(t[xx][yy + i]);
}

// ---------------------------------------------------------------------------
// GEMM tiling: CTA 128x128, 256 threads (8 warps, 4Mx2N, warp 32x64),
// K-block 64, 3-stage cp.async, 2 CTAs/SM (16 warps/SM).
// ---------------------------------------------------------------------------
#define GSTAGES 3
#define KB      64
#define HSTR    72
#define TILEH   (128*HSTR)
#define TILE_B  (TILEH*2)
#define GEMM_SMEM (GSTAGES*2*TILE_B)

#define AT_STR  72
#define AT_BUF  (64*AT_STR*2)

__device__ __forceinline__ void g_load_stage(uint32_t sbase, int s,
                                             const __half* Ag, const __half* Bg,
                                             int k0, int tid)
{
    uint32_t base = sbase + (uint32_t)s * 2 * TILE_B;
#pragma unroll
    for (int i = 0; i < 4; i++) {
        int f = tid + i * 256;          // 0..1023
        int row = f >> 3, c = f & 7;
        cp_async16(base + row * (HSTR * 2) + c * 16,
                   Ag + (size_t)row * CC + k0 + c * 8);
        cp_async16(base + TILE_B + row * (HSTR * 2) + c * 16,
                   Bg + (size_t)row * CC + k0 + c * 8);
    }
    asm volatile("cp.async.commit_group;" ::: "memory");
}

// Shared fp16 GEMM mainloop: warp tile 32x64, acc[2][8][4]
__device__ __forceinline__ void gemm_mainloop(uint32_t sbase,
                                              const __half* Ag, const __half* Bg,
                                              int tid, int wm, int wn, int lane,
                                              float acc[2][8][4])
{
    const int aRow = wm * 32 + (lane & 15);
    const int aCol = ((lane >> 4) & 1) * 8;
    const int bRow = wn * 64 + ((lane >> 4) << 3) + (lane & 7);
    const int bCol = ((lane >> 3) & 1) * 8;

    const int NIT = CC / KB;   // 16
#pragma unroll
    for (int s = 0; s < GSTAGES - 1; s++)
        g_load_stage(sbase, s, Ag, Bg, s * KB, tid);

    for (int it = 0; it < NIT; it++) {
        if (it < NIT - 1)
            asm volatile("cp.async.wait_group %0;" :: "n"(GSTAGES - 2) : "memory");
        else
            asm volatile("cp.async.wait_group 0;" ::: "memory");
        __syncthreads();

        if (it + GSTAGES - 1 < NIT)
            g_load_stage(sbase, (it + GSTAGES - 1) % GSTAGES, Ag, Bg,
                         (it + GSTAGES - 1) * KB, tid);

        const uint32_t Aab = sbase + (uint32_t)(it % GSTAGES) * 2 * TILE_B;
        const uint32_t Bab = Aab + TILE_B;

#pragma unroll
        for (int h = 0; h < 4; h++) {
            uint32_t au[2][4];
#pragma unroll
            for (int mt = 0; mt < 2; mt++)
                ldsm4(au[mt], Aab + (uint32_t)(((aRow + mt * 16) * HSTR
                                                + h * 16 + aCol) * 2));
            uint32_t bu[4][4];
#pragma unroll
            for (int p = 0; p < 4; p++)
                ldsm4(bu[p], Bab + (uint32_t)(((bRow + p * 16) * HSTR
                                               + h * 16 + bCol) * 2));
#pragma unroll
            for (int mt = 0; mt < 2; mt++)
#pragma unroll
                for (int nt = 0; nt < 8; nt++)
                    mma_f16(acc[mt][nt], au[mt][0], au[mt][1], au[mt][2],
                            au[mt][3], bu[nt >> 1][(nt & 1) * 2],
                            bu[nt >> 1][(nt & 1) * 2 + 1]);
        }
    }
}

// ---------------------------------------------------------------------------
// Mega-kernel (256 threads/CTA):
//   bids    0.. 767 : QKV GEMM, DESCENDING-t m-blocks (release g_fq)
//   bids  768..1279 : flash attention, q-tile 128, 8 warps, DESC k-tiles
//   bids 1280..1535 : proj GEMM heavy-first (consume g_fy, target 16)
// ---------------------------------------------------------------------------
__global__ __launch_bounds__(256, 2)
void mega_kernel(const __half* __restrict__ A, const __half* __restrict__ Bt,
                 const float* __restrict__ bias, __half* __restrict__ Yg,
                 const __half* __restrict__ Wp, const float* __restrict__ bp,
                 float* __restrict__ Out)
{
    extern __shared__ __align__(16) __half smh[];
    const uint32_t sbase = s2u(smh);
    const int tid = threadIdx.x;
    const int bid = blockIdx.x;
    const int lane = tid & 31;
    const int r    = lane >> 2;
    const int l4   = lane & 3;

    if (bid < 768) {
        // ================= QKV GEMM (descending-t production) ==============
        const int wid = tid >> 5;
        const int wm  = wid & 3;            // 4 along M
        const int wn  = wid >> 2;           // 2 along N
        const int rank = bid / 24, nblk = bid % 24;
        const int mblock = ((rank & 1) << 4) | (15 - (rank >> 1));
        const int m0 = mblock << 7, n0 = nblk << 7;

        float acc[2][8][4];
#pragma unroll
        for (int mt = 0; mt < 2; mt++)
#pragma unroll
            for (int nt = 0; nt < 8; nt++)
#pragma unroll
                for (int j = 0; j < 4; j++) acc[mt][nt][j] = 0.0f;

        gemm_mainloop(sbase, A + (size_t)m0 * CC, Bt + (size_t)n0 * CC,
                      tid, wm, wn, lane, acc);

        const float QS = 0.125f * 1.44269504089f;
#pragma unroll
        for (int mt = 0; mt < 2; mt++) {
#pragma unroll
            for (int nt = 0; nt < 8; nt++) {
                const int row = m0 + wm * 32 + mt * 16 + r;
                const int c   = n0 + wn * 64 + nt * 8 + 2 * l4;
                const float b0v = __ldg(bias + c);
                const float b1v = __ldg(bias + c + 1);
                float v00 = acc[mt][nt][0] + b0v, v01 = acc[mt][nt][1] + b1v;
                float v10 = acc[mt][nt][2] + b0v, v11 = acc[mt][nt][3] + b1v;
                const int sec = c >> 10;
                const int cs = c & 1023, h = cs >> 6, d0 = cs & 63;
                const int b  = row >> 11;
                const int t0 = row & 2047;
                const int t1 = (row + 8) & 2047;
                if (sec == 2) {
                    __half* vb = g_v + ((size_t)(b * HH + h) * HD) * TT;
                    vb[(size_t)d0 * TT + t0]       = __float2half_rn(v00);
                    vb[(size_t)(d0 + 1) * TT + t0] = __float2half_rn(v01);
                    vb[(size_t)d0 * TT + t1]       = __float2half_rn(v10);
                    vb[(size_t)(d0 + 1) * TT + t1] = __float2half_rn(v11);
                } else {
                    if (sec == 0) { v00 *= QS; v01 *= QS; v10 *= QS; v11 *= QS; }
                    __half* basep = (sec == 0) ? g_q : g_k;
                    __half* p0 = basep + (((size_t)(b * HH + h) * TT + t0) * HD + d0);
                    __half* p1 = basep + (((size_t)(b * HH + h) * TT + t1) * HD + d0);
                    *(uint32_t*)p0 = pack_h2(v00, v01);
                    *(uint32_t*)p1 = pack_h2(v10, v11);
                }
            }
        }
        __syncthreads();
        __threadfence();
        if (tid == 0) atomicAdd(&g_fq[mblock], 1);
        return;
    }

    if (bid >= 1280) {
        // ================= Proj GEMM (consumes g_fy, heavy-first) ===========
        const int pbid = bid - 1280;
        const int wid = tid >> 5;
        const int wm  = wid & 3;
        const int wn  = wid >> 2;
        const int rank = pbid >> 3, nblk = pbid & 7;
        const int mb_w = 15 - (rank >> 1);
        const int b    = rank & 1;
        const int mblock = b * 16 + mb_w;
        const int m0 = mblock << 7, n0 = nblk << 7;

        if (tid == 0) {
            spin_flag(g_fy, mblock, 16);
            __threadfence();
        }
        __syncthreads();

        float acc[2][8][4];
#pragma unroll
        for (int mt = 0; mt < 2; mt++)
#pragma unroll
            for (int nt = 0; nt < 8; nt++)
#pragma unroll
                for (int j = 0; j < 4; j++) acc[mt][nt][j] = 0.0f;

        gemm_mainloop(sbase, Yg + (size_t)m0 * CC, Wp + (size_t)n0 * CC,
                      tid, wm, wn, lane, acc);

#pragma unroll
        for (int mt = 0; mt < 2; mt++) {
#pragma unroll
            for (int nt = 0; nt < 8; nt++) {
                const int row = m0 + wm * 32 + mt * 16 + r;
                const int c   = n0 + wn * 64 + nt * 8 + 2 * l4;
                const float b0v = __ldg(bp + c);
                const float b1v = __ldg(bp + c + 1);
                *(float2*)(Out + (size_t)row * CC + c)
                    = make_float2(acc[mt][nt][0] + b0v, acc[mt][nt][1] + b1v);
                *(float2*)(Out + (size_t)(row + 8) * CC + c)
                    = make_float2(acc[mt][nt][2] + b0v, acc[mt][nt][3] + b1v);
            }
        }
        return;
    }

    // === Flash attention: q-tile 128, 8 warps (16 q-rows each), desc k ====
    {
        const int abid = bid - 768;                 // 0..511
        const int qb   = 15 - (abid >> 5);          // heavy-first, 0..15
        const int bh   = abid & 31;
        const int b    = bh >> 4, h = bh & 15;
        const int qbase = qb * 128;
        const int bqoff  = b * 16;
        const int w = tid >> 5;                     // 0..7

        const uint32_t koff = (uint32_t)AT_BUF;
        const uint32_t PS_B = (uint32_t)(4 * 64 * AT_STR * 2);   // Q staging

        const __half* Qp  = g_q + (size_t)bh * TT * HD;
        const __half* Kp  = g_k + (size_t)bh * TT * HD;
        const __half* Vtp = g_v + (size_t)bh * HD * TT;

        if (tid == 0) {
            spin_flag(g_fq, bqoff + qb, 24);
            __threadfence();
        }
        __syncthreads();

        const int ktop = 2 * qb + 1;                // first (descending) k-tile
        {
            const int kb0 = ktop * 64;
            const uint32_t buf0 = (uint32_t)(ktop & 1);
#pragma unroll
            for (int i = 0; i < 4; i++) {
                int f = tid + i * 256;              // 0..1023
                int row = f >> 3, c = f & 7;
                cp_async16(sbase + PS_B + (uint32_t)(row * AT_STR) * 2 + c * 16,
                           Qp + (size_t)(qbase + row) * HD + c * 8);
            }
#pragma unroll
            for (int i = 0; i < 2; i++) {
                int f = tid + i * 256;              // 0..511
                int row = f >> 3, c = f & 7;
                cp_async16(sbase + buf0 * koff + (uint32_t)(row * AT_STR) * 2 + c * 16,
                           Kp + (size_t)(kb0 + row) * HD + c * 8);
                cp_async16(sbase + 2 * koff + buf0 * koff
                           + (uint32_t)(row * AT_STR) * 2 + c * 16,
                           Vtp + (size_t)row * TT + kb0 + c * 8);
            }
        }
        asm volatile("cp.async.commit_group;" ::: "memory");
        asm volatile("cp.async.wait_group 0;" ::: "memory");
        __syncthreads();

        const int aRowL = lane & 15;
        const int aColL = ((lane >> 4) & 1) * 8;
        const int bRowL = ((lane >> 4) << 3) + (lane & 7);
        const int bColL = ((lane >> 3) & 1) * 8;

        uint32_t aq[4][4];
#pragma unroll
        for (int hc = 0; hc < 4; hc++)
            ldsm4(aq[hc], sbase + PS_B +
                  (uint32_t)(((w * 16 + aRowL) * AT_STR + hc * 16 + aColL) * 2));
        __syncthreads();

        float O[8][4];
#pragma unroll
        for (int nt = 0; nt < 8; nt++)
#pragma unroll
            for (int j = 0; j < 4; j++) O[nt][j] = 0.0f;
        float m0v = -1e30f, m1v = -1e30f, l0v = 0.0f, l1v = 0.0f;

        const int tq0 = qbase + w * 16 + r;
        const int tq1 = tq0 + 8;

        for (int kt = ktop; kt >= 0; kt--) {
            const int kbase = kt * 64;
            const int buf = kt & 1;
            const uint32_t kAddr = sbase + (uint32_t)buf * koff;
            const uint32_t vAddr = sbase + 2 * koff + (uint32_t)buf * koff;
            const bool more = (kt > 0);

            if (more) {
                const int nb = kbase - 64;
                uint32_t kd = sbase + (uint32_t)(buf ^ 1) * koff;
                uint32_t vd = sbase + 2 * koff + (uint32_t)(buf ^ 1) * koff;
#pragma unroll
                for (int i = 0; i < 2; i++) {
                    int f = tid + i * 256;
                    int row = f >> 3, c = f & 7;
                    cp_async16(kd + (uint32_t)(row * AT_STR) * 2 + c * 16,
                               Kp + (size_t)(nb + row) * HD + c * 8);
                    cp_async16(vd + (uint32_t)(row * AT_STR) * 2 + c * 16,
                               Vtp + (size_t)row * TT + nb + c * 8);
                }
                asm volatile("cp.async.commit_group;" ::: "memory");
            }

            // S = Q K^T
            float s[8][4];
#pragma unroll
            for (int nt = 0; nt < 8; nt++)
#pragma unroll
                for (int j = 0; j < 4; j++) s[nt][j] = 0.0f;
#pragma unroll
            for (int hc = 0; hc < 4; hc++) {
                uint32_t ku[4][4];
#pragma unroll
                for (int p = 0; p < 4; p++)
                    ldsm4(ku[p], kAddr + (uint32_t)(((p * 16 + bRowL) * AT_STR
                                                    + hc * 16 + bColL) * 2));
#pragma unroll
                for (int nt = 0; nt < 8; nt++)
                    mma_f16(s[nt], aq[hc][0], aq[hc][1], aq[hc][2], aq[hc][3],
                            ku[nt >> 1][(nt & 1) * 2],
                            ku[nt >> 1][(nt & 1) * 2 + 1]);
            }

            // causal mask (diagonal region only)
            if (kbase + 63 > qbase + w * 16) {
#pragma unroll
                for (int nt = 0; nt < 8; nt++) {
                    int tk = kbase + nt * 8 + 2 * l4;
                    if (tk     > tq0) s[nt][0] = -1e30f;
                    if (tk + 1 > tq0) s[nt][1] = -1e30f;
                    if (tk     > tq1) s[nt][2] = -1e30f;
                    if (tk + 1 > tq1) s[nt][3] = -1e30f;
                }
            }

            // online softmax (log2 domain)
            float ml0 = -1e30f, ml1 = -1e30f;
#pragma unroll
            for (int nt = 0; nt < 8; nt++) {
                ml0 = fmaxf(ml0, fmaxf(s[nt][0], s[nt][1]));
                ml1 = fmaxf(ml1, fmaxf(s[nt][2], s[nt][3]));
            }
            ml0 = fmaxf(ml0, __shfl_xor_sync(0xffffffffu, ml0, 1));
            ml0 = fmaxf(ml0, __shfl_xor_sync(0xffffffffu, ml0, 2));
            ml1 = fmaxf(ml1, __shfl_xor_sync(0xffffffffu, ml1, 1));
            ml1 = fmaxf(ml1, __shfl_xor_sync(0xffffffffu, ml1, 2));
            float mn0 = fmaxf(m0v, ml0), mn1 = fmaxf(m1v, ml1);
            float c0 = ex2(m0v - mn0), c1 = ex2(m1v - mn1);
            float ps0 = 0.0f, ps1 = 0.0f;
#pragma unroll
            for (int nt = 0; nt < 8; nt++) {
                s[nt][0] = ex2(s[nt][0] - mn0); ps0 += s[nt][0];
                s[nt][1] = ex2(s[nt][1] - mn0); ps0 += s[nt][1];
                s[nt][2] = ex2(s[nt][2] - mn1); ps1 += s[nt][2];
                s[nt][3] = ex2(s[nt][3] - mn1); ps1 += s[nt][3];
            }
            ps0 += __shfl_xor_sync(0xffffffffu, ps0, 1);
            ps0 += __shfl_xor_sync(0xffffffffu, ps0, 2);
            ps1 += __shfl_xor_sync(0xffffffffu, ps1, 1);
            ps1 += __shfl_xor_sync(0xffffffffu, ps1, 2);
            l0v = l0v * c0 + ps0; m0v = mn0;
            l1v = l1v * c1 + ps1; m1v = mn1;
#pragma unroll
            for (int nt = 0; nt < 8; nt++) {
                O[nt][0] *= c0; O[nt][1] *= c0;
                O[nt][2] *= c1; O[nt][3] *= c1;
            }

            // P fragments DIRECTLY from S accumulators (identical layouts):
            // A-frag chunk hc = rows {r, r+8}, cols {hc*16+2l4(+1), hc*16+8+2l4(+1)}
            //                = s[2hc][0..3], s[2hc+1][0..3] packed as half2.
            uint32_t ph[4][4];
#pragma unroll
            for (int hc = 0; hc < 4; hc++) {
                ph[hc][0] = pack_h2(s[2 * hc][0],     s[2 * hc][1]);
                ph[hc][1] = pack_h2(s[2 * hc][2],     s[2 * hc][3]);
                ph[hc][2] = pack_h2(s[2 * hc + 1][0], s[2 * hc + 1][1]);
                ph[hc][3] = pack_h2(s[2 * hc + 1][2], s[2 * hc + 1][3]);
            }

            // O += P V (no smem staging for P)
#pragma unroll
            for (int hc = 0; hc < 4; hc++) {
                uint32_t vu[4][4];
#pragma unroll
                for (int p = 0; p < 4; p++)
                    ldsm4(vu[p], vAddr + (uint32_t)(((p * 16 + bRowL) * AT_STR
                                                    + hc * 16 + bColL) * 2));
#pragma unroll
                for (int nt = 0; nt < 8; nt++)
                    mma_f16(O[nt], ph[hc][0], ph[hc][1], ph[hc][2], ph[hc][3],
                            vu[nt >> 1][(nt & 1) * 2],
                            vu[nt >> 1][(nt & 1) * 2 + 1]);
            }

            if (more) {
                asm volatile("cp.async.wait_group 0;" ::: "memory");
                if (tid == 0) {
                    if (kt - 2 >= 0) spin_flag(g_fq, bqoff + ((kt - 2) >> 1), 24);
                    __threadfence();
                }
                __syncthreads();
            }
        }

        // Epilogue: normalize, half y, release g_fy
        const int hb = h * 64;
        const float inv0 = 1.0f / l0v, inv1 = 1.0f / l1v;
        __half* y0 = Yg + (size_t)(b * TT + tq0) * CC;
        __half* y1 = Yg + (size_t)(b * TT + tq1) * CC;
#pragma unroll
        for (int nt = 0; nt < 8; nt++) {
            int c = hb + nt * 8 + 2 * l4;
            *(uint32_t*)(y0 + c) = pack_h2(O[nt][0] * inv0, O[nt][1] * inv0);
            *(uint32_t*)(y1 + c) = pack_h2(O[nt][2] * inv1, O[nt][3] * inv1);
        }
        __syncthreads();
        __threadfence();
        if (tid == 0) atomicAdd(&g_fy[b * 16 + qb], 1);
    }
}

// ---------------------------------------------------------------------------
// Launch
// ---------------------------------------------------------------------------
extern "C" void kernel_launch(void* const* d_in, const int* in_sizes, int n_in,
                              void* d_out, int out_size)
{
    const float* x     = (const float*)d_in[0];
    const float* Wqkv  = (const float*)d_in[1];
    const float* bqkv  = (const float*)d_in[2];
    const float* Wproj = (const float*)d_in[3];
    const float* bproj = (const float*)d_in[4];
    float* out = (float*)d_out;
    (void)in_sizes; (void)n_in; (void)out_size;

    __half *yp, *xp, *wtq, *wtp;
    cudaGetSymbolAddress((void**)&yp,  g_y);
    cudaGetSymbolAddress((void**)&xp,  g_xp);
    cudaGetSymbolAddress((void**)&wtq, g_wtq);
    cudaGetSymbolAddress((void**)&wtp, g_wtp);

    cudaFuncSetAttribute(mega_kernel, cudaFuncAttributeMaxDynamicSharedMemorySize, GEMM_SMEM);

    prep_all<<<4096 + 3072 + 1024, 256>>>(x, Wqkv, Wproj, xp, wtq, wtp);

    mega_kernel<<<768 + 512 + 256, 256, GEMM_SMEM>>>(xp, wtq, bqkv, yp,
                                                     wtp, bproj, out);
}